// round 5
// baseline (speedup 1.0000x reference)
#include <cuda_runtime.h>
#include <cuda_bf16.h>
#include <cstdint>

#define NDV 100000
#define NE  800000
#define H   128
#define OD  40

// ---------------- device scratch (static globals: allocation-free) -------------
__device__ float g_agg[(size_t)NDV * H];     // mean-aggregated neighbor features
__device__ float g_out[(size_t)NDV * H];
__device__ float g_h  [(size_t)NDV * H];
__device__ float g_p  [(size_t)NDV * OD];
__device__ int   g_degi[NDV];
__device__ int   g_rowstart[NDV + 1];
__device__ int   g_cursor[NDV];
__device__ int   g_csr_src[NE];
__device__ float g_inv[NDV];
__device__ float g_sum[H];
__device__ float g_sq [H];
__device__ float g_scale[H];
__device__ float g_shift[H];

// ---------------- helpers ------------------------------------------------------
__device__ __forceinline__ uint32_t s2u(const void* p) {
    uint32_t a;
    asm("{ .reg .u64 t; cvta.to.shared.u64 t, %1; cvt.u32.u64 %0, t; }" : "=r"(a) : "l"(p));
    return a;
}
__device__ __forceinline__ unsigned long long pk2(float lo, float hi) {
    unsigned long long r;
    asm("mov.b64 %0, {%1,%2};" : "=l"(r) : "f"(lo), "f"(hi));
    return r;
}
__device__ __forceinline__ void upk2(unsigned long long v, float &lo, float &hi) {
    asm("mov.b64 {%0,%1}, %2;" : "=f"(lo), "=f"(hi) : "l"(v));
}
__device__ __forceinline__ void fma2(unsigned long long &c, unsigned long long a, unsigned long long b) {
    asm("fma.rn.f32x2 %0, %1, %2, %0;" : "+l"(c) : "l"(a), "l"(b));
}
__device__ __forceinline__ uint32_t pkbf(float a, float b) {
    __nv_bfloat162 t = __halves2bfloat162(__float2bfloat16(a), __float2bfloat16(b));
    return *(uint32_t*)&t;
}
__device__ __forceinline__ float bflo(float x) {
    __nv_bfloat16 h = __float2bfloat16(x);
    return x - __bfloat162float(h);
}
__device__ __forceinline__ void ldmA(uint32_t* r, uint32_t a) {
    asm volatile("ldmatrix.sync.aligned.m8n8.x4.shared.b16 {%0,%1,%2,%3},[%4];"
                 : "=r"(r[0]), "=r"(r[1]), "=r"(r[2]), "=r"(r[3]) : "r"(a));
}
__device__ __forceinline__ void ldmBT(uint32_t* r, uint32_t a) {
    asm volatile("ldmatrix.sync.aligned.m8n8.x4.trans.shared.b16 {%0,%1,%2,%3},[%4];"
                 : "=r"(r[0]), "=r"(r[1]), "=r"(r[2]), "=r"(r[3]) : "r"(a));
}
__device__ __forceinline__ void mmabf(float* d, const uint32_t* a, const uint32_t* b) {
    asm volatile("mma.sync.aligned.m16n8k16.row.col.f32.bf16.bf16.f32 "
                 "{%0,%1,%2,%3},{%4,%5,%6,%7},{%8,%9},{%0,%1,%2,%3};"
                 : "+f"(d[0]), "+f"(d[1]), "+f"(d[2]), "+f"(d[3])
                 : "r"(a[0]), "r"(a[1]), "r"(a[2]), "r"(a[3]), "r"(b[0]), "r"(b[1]));
}

// ---------------- CSR build ----------------------------------------------------
__global__ void k_zero_deg() {
    int i = blockIdx.x * blockDim.x + threadIdx.x;
    if (i < NDV) g_degi[i] = 0;
}
__global__ void k_deg(const int* __restrict__ dst) {
    int e = blockIdx.x * blockDim.x + threadIdx.x;
    if (e < NE) atomicAdd(&g_degi[dst[e]], 1);
}

#define SCAN_T 1024
#define CHUNK ((NDV + SCAN_T - 1) / SCAN_T)    // 98
__global__ __launch_bounds__(SCAN_T, 1)
void k_scan() {
    __shared__ int wsum[32];
    int t = threadIdx.x, lane = t & 31, wid = t >> 5;
    int b = t * CHUNK, e = min(b + CHUNK, NDV);
    int local = 0;
    for (int i = b; i < e; ++i) local += g_degi[i];
    int s = local;
    #pragma unroll
    for (int o = 1; o < 32; o <<= 1) {
        int v = __shfl_up_sync(0xffffffffu, s, o);
        if (lane >= o) s += v;
    }
    if (lane == 31) wsum[wid] = s;
    __syncthreads();
    if (wid == 0) {
        int v = wsum[lane];
        #pragma unroll
        for (int o = 1; o < 32; o <<= 1) {
            int u = __shfl_up_sync(0xffffffffu, v, o);
            if (lane >= o) v += u;
        }
        wsum[lane] = v;
    }
    __syncthreads();
    int excl = s - local + (wid > 0 ? wsum[wid - 1] : 0);
    for (int i = b; i < e; ++i) {
        int d = g_degi[i];
        g_rowstart[i] = excl;
        g_cursor[i]   = excl;
        g_inv[i] = 1.f / fmaxf((float)d, 1.f);
        excl += d;
    }
    if (t == SCAN_T - 1) g_rowstart[NDV] = excl;
    if (t < H) { g_sum[t] = 0.f; g_sq[t] = 0.f; }
}

__global__ void k_scatter(const int* __restrict__ src, const int* __restrict__ dst) {
    int e = blockIdx.x * blockDim.x + threadIdx.x;
    if (e >= NE) return;
    int pos = atomicAdd(&g_cursor[dst[e]], 1);
    g_csr_src[pos] = src[e];
}

// ---------------- CSR mean-aggregation: warp per dst node ----------------------
// writes g_agg row once, pre-multiplied by 1/deg
__global__ void k_aggcsr(const float* __restrict__ hext, int use_gh) {
    int idx = blockIdx.x * blockDim.x + threadIdx.x;
    int n = idx >> 5, lane = idx & 31;
    if (n >= NDV) return;
    const float* h = use_gh ? (const float*)g_h : hext;
    int b = g_rowstart[n], e = g_rowstart[n + 1];
    float4 acc = make_float4(0.f, 0.f, 0.f, 0.f);
    for (int i = b; i < e; ++i) {
        int s = g_csr_src[i];
        float4 v = ((const float4*)(h + (size_t)s * H))[lane];
        acc.x += v.x; acc.y += v.y; acc.z += v.z; acc.w += v.w;
    }
    float iv = g_inv[n];
    acc.x *= iv; acc.y *= iv; acc.z *= iv; acc.w *= iv;
    ((float4*)(g_agg + (size_t)n * H))[lane] = acc;
}

// ================= layers 0/1 GEMM via mma.sync bf16 (3-term split) ============
// D[64,128] per tile = concat(h, agg)[64,256] @ stacked W[256,128]
// fused BN column sum/sumsq epilogue.
#define T64 ((NDV + 63) >> 6)
#define MM_BHI 0
#define MM_BLO 65536
#define MM_AHI 131072
#define MM_ALO 163840
#define MM_STAT 196608
#define MM_TOT (196608 + 1024)

__global__ __launch_bounds__(256, 1)
void k_gemm01mma(const float* __restrict__ Aext, int use_gh,
                 const float* __restrict__ Wself, const float* __restrict__ Wneigh) {
    extern __shared__ char smem[];
    uint32_t sb = s2u(smem);
    float* ssum = (float*)(smem + MM_STAT);
    float* ssq  = ssum + H;
    const int tid = threadIdx.x, lane = tid & 31, wid = tid >> 5;
    const float* A = use_gh ? (const float*)g_h : Aext;

    // ---- stage stacked weights hi/lo: [k=256][n=128], row=256B, chunk ^= (k&7) -
    for (int it = 0; it < 16; ++it) {
        int idx = tid + (it << 8);
        int k = idx >> 4, nc = idx & 15, n0 = nc << 3;
        const float* wsrc = (k < 128) ? (Wself + k * H + n0) : (Wneigh + (k - 128) * H + n0);
        float4 v0 = *(const float4*)(wsrc);
        float4 v1 = *(const float4*)(wsrc + 4);
        uint32_t off = (uint32_t)k * 256 + (uint32_t)((nc ^ (k & 7)) << 4);
        *(uint4*)(smem + MM_BHI + off) = make_uint4(
            pkbf(v0.x, v0.y), pkbf(v0.z, v0.w), pkbf(v1.x, v1.y), pkbf(v1.z, v1.w));
        *(uint4*)(smem + MM_BLO + off) = make_uint4(
            pkbf(bflo(v0.x), bflo(v0.y)), pkbf(bflo(v0.z), bflo(v0.w)),
            pkbf(bflo(v1.x), bflo(v1.y)), pkbf(bflo(v1.z), bflo(v1.w)));
    }
    if (tid < H) { ssum[tid] = 0.f; ssq[tid] = 0.f; }
    __syncthreads();

    const int wm = wid & 1, wn = wid >> 1;
    const int rbase = wm << 5, nbase = wn << 5;
    const int l7 = lane & 7, kp = lane >> 4, l15 = lane & 15;
    const int g = lane >> 2, tq = lane & 3;
    const uint32_t aRowHi = sb + MM_AHI + (uint32_t)(rbase + l15) * 512;
    const uint32_t aRowLo = aRowHi + (MM_ALO - MM_AHI);
    const int nb0 = (nbase >> 3) + kp;
    const uint32_t bch0 = (uint32_t)((nb0 ^ l7) << 4);
    const uint32_t bch1 = (uint32_t)(((nb0 + 2) ^ l7) << 4);
    const uint32_t bHiBase = sb + MM_BHI + (uint32_t)l15 * 256;
    const uint32_t bLoBase = sb + MM_BLO + (uint32_t)l15 * 256;

    const int srow = tid >> 2, skq = (tid & 3) << 6;
    float csum[8], csq[8];
    #pragma unroll
    for (int i = 0; i < 8; ++i) { csum[i] = 0.f; csq[i] = 0.f; }

    for (int t = blockIdx.x; t < T64; t += gridDim.x) {
        int t0 = t << 6;
        __syncthreads();
        // ---- stage A tile hi/lo: [row=64][k=256], row=512B, chunk ^= (row&7) ---
        {
            int rowg = t0 + srow;
            bool valid = rowg < NDV;
            const float* srcp = (skq < 128) ? (A + (size_t)rowg * H + skq)
                                            : (g_agg + (size_t)rowg * H + (skq - 128));
            uint32_t rowoff = (uint32_t)srow * 512;
            int rs = srow & 7;
            #pragma unroll
            for (int j = 0; j < 16; ++j) {
                float4 v = valid ? *(const float4*)(srcp + (j << 2))
                                 : make_float4(0.f, 0.f, 0.f, 0.f);
                int k = skq + (j << 2);
                uint32_t off = rowoff + (uint32_t)(((k >> 3) ^ rs) << 4) + (uint32_t)((k & 7) << 1);
                *(uint2*)(smem + MM_AHI + off) = make_uint2(pkbf(v.x, v.y), pkbf(v.z, v.w));
                *(uint2*)(smem + MM_ALO + off) = make_uint2(pkbf(bflo(v.x), bflo(v.y)),
                                                            pkbf(bflo(v.z), bflo(v.w)));
            }
        }
        __syncthreads();

        float d[2][4][4];
        #pragma unroll
        for (int m = 0; m < 2; ++m)
            #pragma unroll
            for (int nb = 0; nb < 4; ++nb)
                #pragma unroll
                for (int e = 0; e < 4; ++e) d[m][nb][e] = 0.f;

        #pragma unroll 4
        for (int ks = 0; ks < 16; ++ks) {
            uint32_t ach = (uint32_t)((((ks << 1) + kp) ^ l7) << 4);
            uint32_t ahi0[4], ahi1[4], alo0[4], alo1[4];
            ldmA(ahi0, aRowHi + ach);
            ldmA(ahi1, aRowHi + 8192 + ach);
            ldmA(alo0, aRowLo + ach);
            ldmA(alo1, aRowLo + 8192 + ach);
            uint32_t bks = (uint32_t)ks << 12;
            uint32_t bh0[4], bh1[4], bl0[4], bl1[4];
            ldmBT(bh0, bHiBase + bks + bch0);
            ldmBT(bh1, bHiBase + bks + bch1);
            ldmBT(bl0, bLoBase + bks + bch0);
            ldmBT(bl1, bLoBase + bks + bch1);
            mmabf(d[0][0], ahi0, bh0); mmabf(d[0][1], ahi0, bh0 + 2);
            mmabf(d[0][2], ahi0, bh1); mmabf(d[0][3], ahi0, bh1 + 2);
            mmabf(d[1][0], ahi1, bh0); mmabf(d[1][1], ahi1, bh0 + 2);
            mmabf(d[1][2], ahi1, bh1); mmabf(d[1][3], ahi1, bh1 + 2);
            mmabf(d[0][0], ahi0, bl0); mmabf(d[0][1], ahi0, bl0 + 2);
            mmabf(d[0][2], ahi0, bl1); mmabf(d[0][3], ahi0, bl1 + 2);
            mmabf(d[1][0], ahi1, bl0); mmabf(d[1][1], ahi1, bl0 + 2);
            mmabf(d[1][2], ahi1, bl1); mmabf(d[1][3], ahi1, bl1 + 2);
            mmabf(d[0][0], alo0, bh0); mmabf(d[0][1], alo0, bh0 + 2);
            mmabf(d[0][2], alo0, bh1); mmabf(d[0][3], alo0, bh1 + 2);
            mmabf(d[1][0], alo1, bh0); mmabf(d[1][1], alo1, bh0 + 2);
            mmabf(d[1][2], alo1, bh1); mmabf(d[1][3], alo1, bh1 + 2);
        }

        // ---- epilogue + BN partials ----
        #pragma unroll
        for (int m = 0; m < 2; ++m) {
            int row0 = t0 + rbase + (m << 4) + g;
            int row1 = row0 + 8;
            if (row0 < NDV) {
                float* o = g_out + (size_t)row0 * H + nbase + (tq << 1);
                #pragma unroll
                for (int nb = 0; nb < 4; ++nb) {
                    *(float2*)(o + (nb << 3)) = make_float2(d[m][nb][0], d[m][nb][1]);
                    csum[nb * 2 + 0] += d[m][nb][0]; csq[nb * 2 + 0] += d[m][nb][0] * d[m][nb][0];
                    csum[nb * 2 + 1] += d[m][nb][1]; csq[nb * 2 + 1] += d[m][nb][1] * d[m][nb][1];
                }
            }
            if (row1 < NDV) {
                float* o = g_out + (size_t)row1 * H + nbase + (tq << 1);
                #pragma unroll
                for (int nb = 0; nb < 4; ++nb) {
                    *(float2*)(o + (nb << 3)) = make_float2(d[m][nb][2], d[m][nb][3]);
                    csum[nb * 2 + 0] += d[m][nb][2]; csq[nb * 2 + 0] += d[m][nb][2] * d[m][nb][2];
                    csum[nb * 2 + 1] += d[m][nb][3]; csq[nb * 2 + 1] += d[m][nb][3] * d[m][nb][3];
                }
            }
        }
    }

    #pragma unroll
    for (int nb = 0; nb < 4; ++nb)
        #pragma unroll
        for (int j = 0; j < 2; ++j) {
            int col = nbase + (tq << 1) + (nb << 3) + j;
            atomicAdd(&ssum[col], csum[nb * 2 + j]);
            atomicAdd(&ssq[col],  csq[nb * 2 + j]);
        }
    __syncthreads();
    if (tid < H) {
        atomicAdd(&g_sum[tid], ssum[tid]);
        atomicAdd(&g_sq[tid],  ssq[tid]);
    }
}

// bnfin consumes stats AND re-zeroes them (keeps device state replay-invariant)
__global__ void k_bnfin(const float* __restrict__ gamma, const float* __restrict__ beta) {
    int c = threadIdx.x;
    float mean = g_sum[c] * (1.f / NDV);
    float var  = g_sq[c]  * (1.f / NDV) - mean * mean;
    float sc = gamma[c] * rsqrtf(var + 1e-5f);
    g_scale[c] = sc;
    g_shift[c] = beta[c] - mean * sc;
    g_sum[c] = 0.f;
    g_sq[c]  = 0.f;
}

__global__ void k_apply() {
    int i = blockIdx.x * blockDim.x + threadIdx.x;
    if (i >= NDV * 32) return;
    int c4 = i & 31;
    float4 v  = ((const float4*)g_out)[i];
    float4 sc = ((const float4*)g_scale)[c4];
    float4 sh = ((const float4*)g_shift)[c4];
    v.x = fmaxf(fmaf(v.x, sc.x, sh.x), 0.f);
    v.y = fmaxf(fmaf(v.y, sc.y, sh.y), 0.f);
    v.z = fmaxf(fmaf(v.z, sc.z, sh.z), 0.f);
    v.w = fmaxf(fmaf(v.w, sc.w, sh.w), 0.f);
    ((float4*)g_h)[i] = v;
}

// ---------------- layer 2 GEMM (FFMA2) -----------------------------------------
#define TILES64 ((NDV + 63) / 64)
#define SMEM2 ((128 * 128 + 128 * 64) * 4)

__global__ __launch_bounds__(256, 1)
void k_gemm2(const float* __restrict__ Wself, const float* __restrict__ Wneigh,
             const float* __restrict__ bias, float* __restrict__ out) {
    extern __shared__ float sm[];
    float* Bs = sm;
    float* As = sm + 128 * 128;
    int tid = threadIdx.x;

    for (int i = tid; i < 128 * 128 / 4; i += 256) {
        int e = i * 4, k = e >> 7, c = e & 127;
        float4 v = make_float4(0.f, 0.f, 0.f, 0.f);
        if (c < 40)      v = *(const float4*)(Wself  + k * OD + c);
        else if (c < 80) v = *(const float4*)(Wneigh + k * OD + (c - 40));
        *(float4*)(Bs + e) = v;
    }
    __syncthreads();

    const int r = tid & 63, c0 = tid >> 6;
    const int w = tid >> 5, lane = tid & 31;
    const int r0 = w << 3, cc = lane << 2;

    for (int t = blockIdx.x; t < TILES64; t += gridDim.x) {
        int t0 = t * 64;
        __syncthreads();
        {
            int row = t0 + r;
            bool valid = row < NDV;
            const float* arow = (const float*)g_h + (size_t)row * H;
            #pragma unroll
            for (int j = 0; j < 8; ++j) {
                int k = (c0 + (j << 2)) << 2;
                float4 v = valid ? *(const float4*)(arow + k) : make_float4(0.f, 0.f, 0.f, 0.f);
                float* p = As + k * 64 + r;
                p[0] = v.x; p[64] = v.y; p[128] = v.z; p[192] = v.w;
            }
        }
        __syncthreads();

        unsigned long long acc[4][4];
        #pragma unroll
        for (int p = 0; p < 4; p++)
            #pragma unroll
            for (int c = 0; c < 4; c++) acc[p][c] = 0ull;

        #pragma unroll 8
        for (int k = 0; k < 128; ++k) {
            float4 alo = *(const float4*)(As + k * 64 + r0);
            float4 ahi = *(const float4*)(As + k * 64 + r0 + 4);
            float4 bv  = *(const float4*)(Bs + k * 128 + cc);
            unsigned long long a0 = pk2(alo.x, alo.y), a1 = pk2(alo.z, alo.w);
            unsigned long long a2 = pk2(ahi.x, ahi.y), a3 = pk2(ahi.z, ahi.w);
            unsigned long long b0 = pk2(bv.x, bv.x), b1 = pk2(bv.y, bv.y);
            unsigned long long b2 = pk2(bv.z, bv.z), b3 = pk2(bv.w, bv.w);
            fma2(acc[0][0], a0, b0); fma2(acc[0][1], a0, b1);
            fma2(acc[0][2], a0, b2); fma2(acc[0][3], a0, b3);
            fma2(acc[1][0], a1, b0); fma2(acc[1][1], a1, b1);
            fma2(acc[1][2], a1, b2); fma2(acc[1][3], a1, b3);
            fma2(acc[2][0], a2, b0); fma2(acc[2][1], a2, b1);
            fma2(acc[2][2], a2, b2); fma2(acc[2][3], a2, b3);
            fma2(acc[3][0], a3, b0); fma2(acc[3][1], a3, b1);
            fma2(acc[3][2], a3, b2); fma2(acc[3][3], a3, b3);
        }

        #pragma unroll
        for (int p = 0; p < 4; p++) {
            float va[4], vb[4];
            #pragma unroll
            for (int c = 0; c < 4; c++) upk2(acc[p][c], va[c], vb[c]);
            int rowA = t0 + r0 + 2 * p, rowB = rowA + 1;
            if (rowA < NDV) {
                #pragma unroll
                for (int c = 0; c < 4; c++) {
                    int col = cc + c;
                    if (col < 40)      out[(size_t)rowA * OD + col] = va[c] + bias[col];
                    else if (col < 80) g_p[(size_t)rowA * OD + col - 40] = va[c];
                }
            }
            if (rowB < NDV) {
                #pragma unroll
                for (int c = 0; c < 4; c++) {
                    int col = cc + c;
                    if (col < 40)      out[(size_t)rowB * OD + col] = vb[c] + bias[col];
                    else if (col < 80) g_p[(size_t)rowB * OD + col - 40] = vb[c];
                }
            }
        }
    }
}

// layer-2 neighbor sum via CSR: 10 threads per node, 160B-coalesced p reads
__global__ void k_out2csr(float* __restrict__ out) {
    int idx = blockIdx.x * blockDim.x + threadIdx.x;
    if (idx >= NDV * 10) return;
    int n = idx / 10, c4 = idx - n * 10;
    int b = g_rowstart[n], e = g_rowstart[n + 1];
    float4 acc = make_float4(0.f, 0.f, 0.f, 0.f);
    for (int i = b; i < e; ++i) {
        int s = g_csr_src[i];
        float4 v = *(const float4*)(g_p + (size_t)s * OD + c4 * 4);
        acc.x += v.x; acc.y += v.y; acc.z += v.z; acc.w += v.w;
    }
    float iv = g_inv[n];
    float* o = out + (size_t)n * OD + c4 * 4;
    float4 cur = *(float4*)o;
    cur.x += acc.x * iv; cur.y += acc.y * iv;
    cur.z += acc.z * iv; cur.w += acc.w * iv;
    *(float4*)o = cur;
}

// ---------------- host launcher ------------------------------------------------
extern "C" void kernel_launch(void* const* d_in, const int* in_sizes, int n_in,
                              void* d_out, int out_size) {
    const float* feat = (const float*)d_in[0];
    const int*   src  = (const int*)d_in[1];
    const int*   dst  = (const int*)d_in[2];
    const float* Ws0 = (const float*)d_in[3];
    const float* Wn0 = (const float*)d_in[4];
    const float* ga0 = (const float*)d_in[5];
    const float* be0 = (const float*)d_in[6];
    const float* Ws1 = (const float*)d_in[7];
    const float* Wn1 = (const float*)d_in[8];
    const float* ga1 = (const float*)d_in[9];
    const float* be1 = (const float*)d_in[10];
    const float* Ws2 = (const float*)d_in[11];
    const float* Wn2 = (const float*)d_in[12];
    const float* b2  = (const float*)d_in[13];
    float* out = (float*)d_out;

    cudaFuncSetAttribute(k_gemm01mma, cudaFuncAttributeMaxDynamicSharedMemorySize, MM_TOT);
    cudaFuncSetAttribute(k_gemm2,     cudaFuncAttributeMaxDynamicSharedMemorySize, SMEM2);

    const int TB = 256;
    // CSR build (per call; deterministic up to fp-sum order)
    k_zero_deg<<<(NDV + TB - 1) / TB, TB>>>();
    k_deg<<<(NE + TB - 1) / TB, TB>>>(dst);
    k_scan<<<1, SCAN_T>>>();
    k_scatter<<<(NE + TB - 1) / TB, TB>>>(src, dst);

    // ---- layer 0 ----
    k_aggcsr<<<(NDV * 32 + TB - 1) / TB, TB>>>(feat, 0);
    k_gemm01mma<<<148, 256, MM_TOT>>>(feat, 0, Ws0, Wn0);
    k_bnfin<<<1, 128>>>(ga0, be0);
    k_apply<<<(NDV * 32 + TB - 1) / TB, TB>>>();

    // ---- layer 1 ----
    k_aggcsr<<<(NDV * 32 + TB - 1) / TB, TB>>>(nullptr, 1);
    k_gemm01mma<<<148, 256, MM_TOT>>>(nullptr, 1, Ws1, Wn1);
    k_bnfin<<<1, 128>>>(ga1, be1);
    k_apply<<<(NDV * 32 + TB - 1) / TB, TB>>>();

    // ---- layer 2 ----
    k_gemm2<<<148, 256, SMEM2>>>(Ws2, Wn2, b2, out);
    k_out2csr<<<(NDV * 10 + TB - 1) / TB, TB>>>(out);

    (void)in_sizes; (void)n_in; (void)out_size;
}

// round 6
// speedup vs baseline: 1.0903x; 1.0903x over previous
#include <cuda_runtime.h>
#include <cuda_bf16.h>
#include <cstdint>

#define NDV 100000
#define NE  800000
#define H   128
#define OD  40

// ---------------- device scratch (static globals: allocation-free) -------------
__device__ float g_agg[(size_t)NDV * H];
__device__ float g_out[(size_t)NDV * H];
__device__ float g_p  [(size_t)NDV * OD];
__device__ float g_deg[NDV];
__device__ float g_inv[NDV];
__device__ float g_sum[H];      // zero-init at load; k_bnfin re-zeroes after use
__device__ float g_sq [H];
__device__ float g_scale[H];
__device__ float g_shift[H];

// ---------------- helpers ------------------------------------------------------
__device__ __forceinline__ uint32_t s2u(const void* p) {
    uint32_t a;
    asm("{ .reg .u64 t; cvta.to.shared.u64 t, %1; cvt.u32.u64 %0, t; }" : "=r"(a) : "l"(p));
    return a;
}
__device__ __forceinline__ unsigned long long pk2(float lo, float hi) {
    unsigned long long r;
    asm("mov.b64 %0, {%1,%2};" : "=l"(r) : "f"(lo), "f"(hi));
    return r;
}
__device__ __forceinline__ void upk2(unsigned long long v, float &lo, float &hi) {
    asm("mov.b64 {%0,%1}, %2;" : "=f"(lo), "=f"(hi) : "l"(v));
}
__device__ __forceinline__ void fma2(unsigned long long &c, unsigned long long a, unsigned long long b) {
    asm("fma.rn.f32x2 %0, %1, %2, %0;" : "+l"(c) : "l"(a), "l"(b));
}
__device__ __forceinline__ void red4(float* p, float x, float y, float z, float w) {
    asm volatile("red.global.add.v4.f32 [%0], {%1,%2,%3,%4};"
                 :: "l"(p), "f"(x), "f"(y), "f"(z), "f"(w) : "memory");
}
__device__ __forceinline__ uint32_t pkbf(float a, float b) {
    __nv_bfloat162 t = __halves2bfloat162(__float2bfloat16(a), __float2bfloat16(b));
    return *(uint32_t*)&t;
}
__device__ __forceinline__ float bflo(float x) {
    __nv_bfloat16 h = __float2bfloat16(x);
    return x - __bfloat162float(h);
}
__device__ __forceinline__ void ldmA(uint32_t* r, uint32_t a) {
    asm volatile("ldmatrix.sync.aligned.m8n8.x4.shared.b16 {%0,%1,%2,%3},[%4];"
                 : "=r"(r[0]), "=r"(r[1]), "=r"(r[2]), "=r"(r[3]) : "r"(a));
}
__device__ __forceinline__ void ldmBT(uint32_t* r, uint32_t a) {
    asm volatile("ldmatrix.sync.aligned.m8n8.x4.trans.shared.b16 {%0,%1,%2,%3},[%4];"
                 : "=r"(r[0]), "=r"(r[1]), "=r"(r[2]), "=r"(r[3]) : "r"(a));
}
__device__ __forceinline__ void mmabf(float* d, const uint32_t* a, const uint32_t* b) {
    asm volatile("mma.sync.aligned.m16n8k16.row.col.f32.bf16.bf16.f32 "
                 "{%0,%1,%2,%3},{%4,%5,%6,%7},{%8,%9},{%0,%1,%2,%3};"
                 : "+f"(d[0]), "+f"(d[1]), "+f"(d[2]), "+f"(d[3])
                 : "r"(a[0]), "r"(a[1]), "r"(a[2]), "r"(a[3]), "r"(b[0]), "r"(b[1]));
}
__device__ __forceinline__ float4 bn4(float4 v, float4 sc, float4 sh) {
    v.x = fmaxf(fmaf(v.x, sc.x, sh.x), 0.f);
    v.y = fmaxf(fmaf(v.y, sc.y, sh.y), 0.f);
    v.z = fmaxf(fmaf(v.z, sc.z, sh.z), 0.f);
    v.w = fmaxf(fmaf(v.w, sc.w, sh.w), 0.f);
    return v;
}

// ---------------- small kernels ------------------------------------------------
__global__ void k_zero_deg() {
    int i = blockIdx.x * blockDim.x + threadIdx.x;
    if (i < NDV) g_deg[i] = 0.f;
}
__global__ void k_zero_agg() {
    int i = blockIdx.x * blockDim.x + threadIdx.x;
    if (i < NDV * H / 4) ((float4*)g_agg)[i] = make_float4(0.f, 0.f, 0.f, 0.f);
}
__global__ void k_deg(const int* __restrict__ dst) {
    int e = blockIdx.x * blockDim.x + threadIdx.x;
    if (e < NE) atomicAdd(&g_deg[dst[e]], 1.f);
}
__global__ void k_inv() {
    int i = blockIdx.x * blockDim.x + threadIdx.x;
    if (i < NDV) g_inv[i] = 1.f / fmaxf(g_deg[i], 1.f);
}

// warp-per-edge gather + vector red scatter; optional fused BN+ReLU on source
__global__ void k_agg(const int* __restrict__ src, const int* __restrict__ dst,
                      const float* __restrict__ hext, int use_bn) {
    int idx = blockIdx.x * blockDim.x + threadIdx.x;
    int e = idx >> 5, lane = idx & 31;
    if (e >= NE) return;
    const float* h = use_bn ? (const float*)g_out : hext;
    int s = src[e], d = dst[e];
    float4 v = ((const float4*)(h + (size_t)s * H))[lane];
    if (use_bn) {
        float4 sc = ((const float4*)g_scale)[lane];
        float4 sh = ((const float4*)g_shift)[lane];
        v = bn4(v, sc, sh);
    }
    float* o = g_agg + (size_t)d * H + lane * 4;
    red4(o, v.x, v.y, v.z, v.w);
}

// ================= layers 0/1 GEMM via mma.sync bf16 (3-term split) ============
// D[64,128] per tile = concat(act(A), agg*inv)[64,256] @ stacked W[256,128]
// act = identity (layer 0) or BN+ReLU (layer 1). Fused BN-stat epilogue.
#define T64 ((NDV + 63) >> 6)
#define MM_BHI 0
#define MM_BLO 65536
#define MM_AHI 131072
#define MM_ALO 163840
#define MM_STAT 196608
#define MM_TOT (196608 + 1024)

__global__ __launch_bounds__(256, 1)
void k_gemm01mma(const float* __restrict__ Aext, int use_bn,
                 const float* __restrict__ Wself, const float* __restrict__ Wneigh) {
    extern __shared__ char smem[];
    uint32_t sb = s2u(smem);
    float* ssum = (float*)(smem + MM_STAT);
    float* ssq  = ssum + H;
    const int tid = threadIdx.x, lane = tid & 31, wid = tid >> 5;
    const float* A = use_bn ? (const float*)g_out : Aext;

    // ---- stage stacked weights hi/lo ----
    for (int it = 0; it < 16; ++it) {
        int idx = tid + (it << 8);
        int k = idx >> 4, nc = idx & 15, n0 = nc << 3;
        const float* wsrc = (k < 128) ? (Wself + k * H + n0) : (Wneigh + (k - 128) * H + n0);
        float4 v0 = *(const float4*)(wsrc);
        float4 v1 = *(const float4*)(wsrc + 4);
        uint32_t off = (uint32_t)k * 256 + (uint32_t)((nc ^ (k & 7)) << 4);
        *(uint4*)(smem + MM_BHI + off) = make_uint4(
            pkbf(v0.x, v0.y), pkbf(v0.z, v0.w), pkbf(v1.x, v1.y), pkbf(v1.z, v1.w));
        *(uint4*)(smem + MM_BLO + off) = make_uint4(
            pkbf(bflo(v0.x), bflo(v0.y)), pkbf(bflo(v0.z), bflo(v0.w)),
            pkbf(bflo(v1.x), bflo(v1.y)), pkbf(bflo(v1.z), bflo(v1.w)));
    }
    if (tid < H) { ssum[tid] = 0.f; ssq[tid] = 0.f; }
    __syncthreads();

    const int wm = wid & 1, wn = wid >> 1;
    const int rbase = wm << 5, nbase = wn << 5;
    const int l7 = lane & 7, kp = lane >> 4, l15 = lane & 15;
    const int g = lane >> 2, tq = lane & 3;
    const uint32_t aRowHi = sb + MM_AHI + (uint32_t)(rbase + l15) * 512;
    const uint32_t aRowLo = aRowHi + (MM_ALO - MM_AHI);
    const int nb0 = (nbase >> 3) + kp;
    const uint32_t bch0 = (uint32_t)((nb0 ^ l7) << 4);
    const uint32_t bch1 = (uint32_t)(((nb0 + 2) ^ l7) << 4);
    const uint32_t bHiBase = sb + MM_BHI + (uint32_t)l15 * 256;
    const uint32_t bLoBase = sb + MM_BLO + (uint32_t)l15 * 256;

    const int srow = tid >> 2, skq = (tid & 3) << 6;
    const bool selfHalf = skq < 128;
    float csum[8], csq[8];
    #pragma unroll
    for (int i = 0; i < 8; ++i) { csum[i] = 0.f; csq[i] = 0.f; }

    for (int t = blockIdx.x; t < T64; t += gridDim.x) {
        int t0 = t << 6;
        __syncthreads();
        // ---- stage A tile hi/lo ----
        {
            int rowg = t0 + srow;
            bool valid = rowg < NDV;
            float iv = (valid && !selfHalf) ? g_inv[rowg] : 1.f;
            const float* srcp = selfHalf ? (A + (size_t)rowg * H + skq)
                                         : (g_agg + (size_t)rowg * H + (skq - 128));
            uint32_t rowoff = (uint32_t)srow * 512;
            int rs = srow & 7;
            #pragma unroll
            for (int j = 0; j < 16; ++j) {
                float4 v = valid ? *(const float4*)(srcp + (j << 2))
                                 : make_float4(0.f, 0.f, 0.f, 0.f);
                int k = skq + (j << 2);
                if (selfHalf) {
                    if (use_bn) {
                        float4 sc = *(const float4*)(g_scale + k);
                        float4 sh = *(const float4*)(g_shift + k);
                        v = bn4(v, sc, sh);
                    }
                } else {
                    v.x *= iv; v.y *= iv; v.z *= iv; v.w *= iv;
                }
                uint32_t off = rowoff + (uint32_t)(((k >> 3) ^ rs) << 4) + (uint32_t)((k & 7) << 1);
                *(uint2*)(smem + MM_AHI + off) = make_uint2(pkbf(v.x, v.y), pkbf(v.z, v.w));
                *(uint2*)(smem + MM_ALO + off) = make_uint2(pkbf(bflo(v.x), bflo(v.y)),
                                                            pkbf(bflo(v.z), bflo(v.w)));
            }
        }
        __syncthreads();

        float d[2][4][4];
        #pragma unroll
        for (int m = 0; m < 2; ++m)
            #pragma unroll
            for (int nb = 0; nb < 4; ++nb)
                #pragma unroll
                for (int e = 0; e < 4; ++e) d[m][nb][e] = 0.f;

        #pragma unroll 4
        for (int ks = 0; ks < 16; ++ks) {
            uint32_t ach = (uint32_t)((((ks << 1) + kp) ^ l7) << 4);
            uint32_t ahi0[4], ahi1[4], alo0[4], alo1[4];
            ldmA(ahi0, aRowHi + ach);
            ldmA(ahi1, aRowHi + 8192 + ach);
            ldmA(alo0, aRowLo + ach);
            ldmA(alo1, aRowLo + 8192 + ach);
            uint32_t bks = (uint32_t)ks << 12;
            uint32_t bh0[4], bh1[4], bl0[4], bl1[4];
            ldmBT(bh0, bHiBase + bks + bch0);
            ldmBT(bh1, bHiBase + bks + bch1);
            ldmBT(bl0, bLoBase + bks + bch0);
            ldmBT(bl1, bLoBase + bks + bch1);
            mmabf(d[0][0], ahi0, bh0); mmabf(d[0][1], ahi0, bh0 + 2);
            mmabf(d[0][2], ahi0, bh1); mmabf(d[0][3], ahi0, bh1 + 2);
            mmabf(d[1][0], ahi1, bh0); mmabf(d[1][1], ahi1, bh0 + 2);
            mmabf(d[1][2], ahi1, bh1); mmabf(d[1][3], ahi1, bh1 + 2);
            mmabf(d[0][0], ahi0, bl0); mmabf(d[0][1], ahi0, bl0 + 2);
            mmabf(d[0][2], ahi0, bl1); mmabf(d[0][3], ahi0, bl1 + 2);
            mmabf(d[1][0], ahi1, bl0); mmabf(d[1][1], ahi1, bl0 + 2);
            mmabf(d[1][2], ahi1, bl1); mmabf(d[1][3], ahi1, bl1 + 2);
            mmabf(d[0][0], alo0, bh0); mmabf(d[0][1], alo0, bh0 + 2);
            mmabf(d[0][2], alo0, bh1); mmabf(d[0][3], alo0, bh1 + 2);
            mmabf(d[1][0], alo1, bh0); mmabf(d[1][1], alo1, bh0 + 2);
            mmabf(d[1][2], alo1, bh1); mmabf(d[1][3], alo1, bh1 + 2);
        }

        // ---- epilogue + BN partials ----
        #pragma unroll
        for (int m = 0; m < 2; ++m) {
            int row0 = t0 + rbase + (m << 4) + g;
            int row1 = row0 + 8;
            if (row0 < NDV) {
                float* o = g_out + (size_t)row0 * H + nbase + (tq << 1);
                #pragma unroll
                for (int nb = 0; nb < 4; ++nb) {
                    *(float2*)(o + (nb << 3)) = make_float2(d[m][nb][0], d[m][nb][1]);
                    csum[nb * 2 + 0] += d[m][nb][0]; csq[nb * 2 + 0] += d[m][nb][0] * d[m][nb][0];
                    csum[nb * 2 + 1] += d[m][nb][1]; csq[nb * 2 + 1] += d[m][nb][1] * d[m][nb][1];
                }
            }
            if (row1 < NDV) {
                float* o = g_out + (size_t)row1 * H + nbase + (tq << 1);
                #pragma unroll
                for (int nb = 0; nb < 4; ++nb) {
                    *(float2*)(o + (nb << 3)) = make_float2(d[m][nb][2], d[m][nb][3]);
                    csum[nb * 2 + 0] += d[m][nb][2]; csq[nb * 2 + 0] += d[m][nb][2] * d[m][nb][2];
                    csum[nb * 2 + 1] += d[m][nb][3]; csq[nb * 2 + 1] += d[m][nb][3] * d[m][nb][3];
                }
            }
        }
    }

    #pragma unroll
    for (int nb = 0; nb < 4; ++nb)
        #pragma unroll
        for (int j = 0; j < 2; ++j) {
            int col = nbase + (tq << 1) + (nb << 3) + j;
            atomicAdd(&ssum[col], csum[nb * 2 + j]);
            atomicAdd(&ssq[col],  csq[nb * 2 + j]);
        }
    __syncthreads();
    if (tid < H) {
        atomicAdd(&g_sum[tid], ssum[tid]);
        atomicAdd(&g_sq[tid],  ssq[tid]);
    }
}

// consumes stats AND re-zeroes them (replay-invariant)
__global__ void k_bnfin(const float* __restrict__ gamma, const float* __restrict__ beta) {
    int c = threadIdx.x;
    float mean = g_sum[c] * (1.f / NDV);
    float var  = g_sq[c]  * (1.f / NDV) - mean * mean;
    float sc = gamma[c] * rsqrtf(var + 1e-5f);
    g_scale[c] = sc;
    g_shift[c] = beta[c] - mean * sc;
    g_sum[c] = 0.f;
    g_sq[c]  = 0.f;
}

// ---------------- layer 2 GEMM (FFMA2) — BN1+ReLU fused into staging -----------
#define TILES64 ((NDV + 63) / 64)
#define SMEM2 ((128 * 128 + 128 * 64) * 4)

__global__ __launch_bounds__(256, 1)
void k_gemm2(const float* __restrict__ Wself, const float* __restrict__ Wneigh,
             const float* __restrict__ bias, float* __restrict__ out) {
    extern __shared__ float sm[];
    float* Bs = sm;
    float* As = sm + 128 * 128;
    int tid = threadIdx.x;

    for (int i = tid; i < 128 * 128 / 4; i += 256) {
        int e = i * 4, k = e >> 7, c = e & 127;
        float4 v = make_float4(0.f, 0.f, 0.f, 0.f);
        if (c < 40)      v = *(const float4*)(Wself  + k * OD + c);
        else if (c < 80) v = *(const float4*)(Wneigh + k * OD + (c - 40));
        *(float4*)(Bs + e) = v;
    }
    __syncthreads();

    const int r = tid & 63, c0 = tid >> 6;
    const int w = tid >> 5, lane = tid & 31;
    const int r0 = w << 3, cc = lane << 2;

    for (int t = blockIdx.x; t < TILES64; t += gridDim.x) {
        int t0 = t * 64;
        __syncthreads();
        {
            int row = t0 + r;
            bool valid = row < NDV;
            const float* arow = (const float*)g_out + (size_t)row * H;
            #pragma unroll
            for (int j = 0; j < 8; ++j) {
                int k = (c0 + (j << 2)) << 2;
                float4 v = valid ? *(const float4*)(arow + k) : make_float4(0.f, 0.f, 0.f, 0.f);
                float4 sc = *(const float4*)(g_scale + k);
                float4 sh = *(const float4*)(g_shift + k);
                v = bn4(v, sc, sh);
                float* p = As + k * 64 + r;
                p[0] = v.x; p[64] = v.y; p[128] = v.z; p[192] = v.w;
            }
        }
        __syncthreads();

        unsigned long long acc[4][4];
        #pragma unroll
        for (int p = 0; p < 4; p++)
            #pragma unroll
            for (int c = 0; c < 4; c++) acc[p][c] = 0ull;

        #pragma unroll 8
        for (int k = 0; k < 128; ++k) {
            float4 alo = *(const float4*)(As + k * 64 + r0);
            float4 ahi = *(const float4*)(As + k * 64 + r0 + 4);
            float4 bv  = *(const float4*)(Bs + k * 128 + cc);
            unsigned long long a0 = pk2(alo.x, alo.y), a1 = pk2(alo.z, alo.w);
            unsigned long long a2 = pk2(ahi.x, ahi.y), a3 = pk2(ahi.z, ahi.w);
            unsigned long long b0 = pk2(bv.x, bv.x), b1 = pk2(bv.y, bv.y);
            unsigned long long b2 = pk2(bv.z, bv.z), b3 = pk2(bv.w, bv.w);
            fma2(acc[0][0], a0, b0); fma2(acc[0][1], a0, b1);
            fma2(acc[0][2], a0, b2); fma2(acc[0][3], a0, b3);
            fma2(acc[1][0], a1, b0); fma2(acc[1][1], a1, b1);
            fma2(acc[1][2], a1, b2); fma2(acc[1][3], a1, b3);
            fma2(acc[2][0], a2, b0); fma2(acc[2][1], a2, b1);
            fma2(acc[2][2], a2, b2); fma2(acc[2][3], a2, b3);
            fma2(acc[3][0], a3, b0); fma2(acc[3][1], a3, b1);
            fma2(acc[3][2], a3, b2); fma2(acc[3][3], a3, b3);
        }

        #pragma unroll
        for (int p = 0; p < 4; p++) {
            float va[4], vb[4];
            #pragma unroll
            for (int c = 0; c < 4; c++) upk2(acc[p][c], va[c], vb[c]);
            int rowA = t0 + r0 + 2 * p, rowB = rowA + 1;
            if (rowA < NDV) {
                #pragma unroll
                for (int c = 0; c < 4; c++) {
                    int col = cc + c;
                    if (col < 40)      out[(size_t)rowA * OD + col] = va[c] + bias[col];
                    else if (col < 80) g_p[(size_t)rowA * OD + col - 40] = va[c];
                }
            }
            if (rowB < NDV) {
                #pragma unroll
                for (int c = 0; c < 4; c++) {
                    int col = cc + c;
                    if (col < 40)      out[(size_t)rowB * OD + col] = vb[c] + bias[col];
                    else if (col < 80) g_p[(size_t)rowB * OD + col - 40] = vb[c];
                }
            }
        }
    }
}

// out[dst] += p[src] * inv_deg[dst]
__global__ void k_edge2(const int* __restrict__ src, const int* __restrict__ dst,
                        float* __restrict__ out) {
    int idx = blockIdx.x * blockDim.x + threadIdx.x;
    if (idx >= NE * 10) return;
    int e = idx / 10, c4 = idx - e * 10;
    int s = src[e], d = dst[e];
    float iv = g_inv[d];
    float4 v = *(const float4*)(g_p + (size_t)s * OD + c4 * 4);
    float* o = out + (size_t)d * OD + c4 * 4;
    red4(o, v.x * iv, v.y * iv, v.z * iv, v.w * iv);
}

// ---------------- host launcher ------------------------------------------------
extern "C" void kernel_launch(void* const* d_in, const int* in_sizes, int n_in,
                              void* d_out, int out_size) {
    const float* feat = (const float*)d_in[0];
    const int*   src  = (const int*)d_in[1];
    const int*   dst  = (const int*)d_in[2];
    const float* Ws0 = (const float*)d_in[3];
    const float* Wn0 = (const float*)d_in[4];
    const float* ga0 = (const float*)d_in[5];
    const float* be0 = (const float*)d_in[6];
    const float* Ws1 = (const float*)d_in[7];
    const float* Wn1 = (const float*)d_in[8];
    const float* ga1 = (const float*)d_in[9];
    const float* be1 = (const float*)d_in[10];
    const float* Ws2 = (const float*)d_in[11];
    const float* Wn2 = (const float*)d_in[12];
    const float* b2  = (const float*)d_in[13];
    float* out = (float*)d_out;

    cudaFuncSetAttribute(k_gemm01mma, cudaFuncAttributeMaxDynamicSharedMemorySize, MM_TOT);
    cudaFuncSetAttribute(k_gemm2,     cudaFuncAttributeMaxDynamicSharedMemorySize, SMEM2);

    const int TB = 256;
    k_zero_deg<<<(NDV + TB - 1) / TB, TB>>>();
    k_deg<<<(NE + TB - 1) / TB, TB>>>(dst);
    k_inv<<<(NDV + TB - 1) / TB, TB>>>();

    // ---- layer 0 ----
    k_zero_agg<<<(NDV * H / 4 + TB - 1) / TB, TB>>>();
    k_agg<<<((size_t)NE * 32 + TB - 1) / TB, TB>>>(src, dst, feat, 0);
    k_gemm01mma<<<148, 256, MM_TOT>>>(feat, 0, Ws0, Wn0);
    k_bnfin<<<1, 128>>>(ga0, be0);

    // ---- layer 1 (BN0+ReLU applied on the fly from g_out) ----
    k_zero_agg<<<(NDV * H / 4 + TB - 1) / TB, TB>>>();
    k_agg<<<((size_t)NE * 32 + TB - 1) / TB, TB>>>(src, dst, nullptr, 1);
    k_gemm01mma<<<148, 256, MM_TOT>>>(nullptr, 1, Ws1, Wn1);
    k_bnfin<<<1, 128>>>(ga1, be1);

    // ---- layer 2 (BN1+ReLU fused into staging) ----
    k_gemm2<<<148, 256, SMEM2>>>(Ws2, Wn2, b2, out);
    k_edge2<<<((size_t)NE * 10 + TB - 1) / TB, TB>>>(src, dst, out);

    (void)in_sizes; (void)n_in; (void)out_size;
}

// round 7
// speedup vs baseline: 1.1075x; 1.0158x over previous
#include <cuda_runtime.h>
#include <cuda_bf16.h>
#include <cstdint>

#define NDV 100000
#define NE  800000
#define H   128
#define OD  40

// ---------------- device scratch (static globals: allocation-free) -------------
__device__ float g_agg[(size_t)NDV * H];
__device__ float g_out[(size_t)NDV * H];
__device__ float g_h  [(size_t)NDV * H];
__device__ float g_p  [(size_t)NDV * OD];
__device__ float g_deg[NDV];
__device__ float g_inv[NDV];
__device__ float g_sum[H];      // zero at load; k_bnfin re-zeroes after consuming
__device__ float g_sq [H];
__device__ float g_scale[H];
__device__ float g_shift[H];

// ---------------- helpers ------------------------------------------------------
__device__ __forceinline__ uint32_t s2u(const void* p) {
    uint32_t a;
    asm("{ .reg .u64 t; cvta.to.shared.u64 t, %1; cvt.u32.u64 %0, t; }" : "=r"(a) : "l"(p));
    return a;
}
__device__ __forceinline__ unsigned long long pk2(float lo, float hi) {
    unsigned long long r;
    asm("mov.b64 %0, {%1,%2};" : "=l"(r) : "f"(lo), "f"(hi));
    return r;
}
__device__ __forceinline__ void upk2(unsigned long long v, float &lo, float &hi) {
    asm("mov.b64 {%0,%1}, %2;" : "=f"(lo), "=f"(hi) : "l"(v));
}
__device__ __forceinline__ void fma2(unsigned long long &c, unsigned long long a, unsigned long long b) {
    asm("fma.rn.f32x2 %0, %1, %2, %0;" : "+l"(c) : "l"(a), "l"(b));
}
__device__ __forceinline__ void red4(float* p, float x, float y, float z, float w) {
    asm volatile("red.global.add.v4.f32 [%0], {%1,%2,%3,%4};"
                 :: "l"(p), "f"(x), "f"(y), "f"(z), "f"(w) : "memory");
}
__device__ __forceinline__ uint32_t pkbf(float a, float b) {
    __nv_bfloat162 t = __halves2bfloat162(__float2bfloat16(a), __float2bfloat16(b));
    return *(uint32_t*)&t;
}
__device__ __forceinline__ float bflo(float x) {
    __nv_bfloat16 h = __float2bfloat16(x);
    return x - __bfloat162float(h);
}
__device__ __forceinline__ void ldmA(uint32_t* r, uint32_t a) {
    asm volatile("ldmatrix.sync.aligned.m8n8.x4.shared.b16 {%0,%1,%2,%3},[%4];"
                 : "=r"(r[0]), "=r"(r[1]), "=r"(r[2]), "=r"(r[3]) : "r"(a));
}
__device__ __forceinline__ void ldmBT(uint32_t* r, uint32_t a) {
    asm volatile("ldmatrix.sync.aligned.m8n8.x4.trans.shared.b16 {%0,%1,%2,%3},[%4];"
                 : "=r"(r[0]), "=r"(r[1]), "=r"(r[2]), "=r"(r[3]) : "r"(a));
}
__device__ __forceinline__ void mmabf(float* d, const uint32_t* a, const uint32_t* b) {
    asm volatile("mma.sync.aligned.m16n8k16.row.col.f32.bf16.bf16.f32 "
                 "{%0,%1,%2,%3},{%4,%5,%6,%7},{%8,%9},{%0,%1,%2,%3};"
                 : "+f"(d[0]), "+f"(d[1]), "+f"(d[2]), "+f"(d[3])
                 : "r"(a[0]), "r"(a[1]), "r"(a[2]), "r"(a[3]), "r"(b[0]), "r"(b[1]));
}

// ---------------- small kernels ------------------------------------------------
__global__ void k_zero_deg() {
    int i = blockIdx.x * blockDim.x + threadIdx.x;
    if (i < NDV) g_deg[i] = 0.f;
}
__global__ void k_zero_agg() {
    int i = blockIdx.x * blockDim.x + threadIdx.x;
    if (i < NDV * H / 4) ((float4*)g_agg)[i] = make_float4(0.f, 0.f, 0.f, 0.f);
}
__global__ void k_deg(const int* __restrict__ dst) {
    int e = blockIdx.x * blockDim.x + threadIdx.x;
    if (e < NE) atomicAdd(&g_deg[dst[e]], 1.f);
}
__global__ void k_inv() {
    int i = blockIdx.x * blockDim.x + threadIdx.x;
    if (i < NDV) g_inv[i] = 1.f / fmaxf(g_deg[i], 1.f);
}

// warp-per-edge gather + vector red scatter (NO fusion: keep it 6 instructions)
__global__ void k_agg(const int* __restrict__ src, const int* __restrict__ dst,
                      const float* __restrict__ hext, int use_gh) {
    int idx = blockIdx.x * blockDim.x + threadIdx.x;
    int e = idx >> 5, lane = idx & 31;
    if (e >= NE) return;
    const float* h = use_gh ? (const float*)g_h : hext;
    int s = src[e], d = dst[e];
    float4 v = ((const float4*)(h + (size_t)s * H))[lane];
    float* o = g_agg + (size_t)d * H + lane * 4;
    red4(o, v.x, v.y, v.z, v.w);
}

// ================= layers 0/1 GEMM via mma.sync bf16 (3-term split) ============
// D[64,128] per tile = concat(A, agg*inv)[64,256] @ stacked W[256,128]
// fused BN column sum/sumsq epilogue (register partials -> smem -> global).
#define T64 ((NDV + 63) >> 6)
#define MM_BHI 0
#define MM_BLO 65536
#define MM_AHI 131072
#define MM_ALO 163840
#define MM_STAT 196608
#define MM_TOT (196608 + 1024)

__global__ __launch_bounds__(256, 1)
void k_gemm01mma(const float* __restrict__ Aext, int use_gh,
                 const float* __restrict__ Wself, const float* __restrict__ Wneigh) {
    extern __shared__ char smem[];
    uint32_t sb = s2u(smem);
    float* ssum = (float*)(smem + MM_STAT);
    float* ssq  = ssum + H;
    const int tid = threadIdx.x, lane = tid & 31, wid = tid >> 5;
    const float* A = use_gh ? (const float*)g_h : Aext;

    // ---- stage stacked weights hi/lo ----
    for (int it = 0; it < 16; ++it) {
        int idx = tid + (it << 8);
        int k = idx >> 4, nc = idx & 15, n0 = nc << 3;
        const float* wsrc = (k < 128) ? (Wself + k * H + n0) : (Wneigh + (k - 128) * H + n0);
        float4 v0 = *(const float4*)(wsrc);
        float4 v1 = *(const float4*)(wsrc + 4);
        uint32_t off = (uint32_t)k * 256 + (uint32_t)((nc ^ (k & 7)) << 4);
        *(uint4*)(smem + MM_BHI + off) = make_uint4(
            pkbf(v0.x, v0.y), pkbf(v0.z, v0.w), pkbf(v1.x, v1.y), pkbf(v1.z, v1.w));
        *(uint4*)(smem + MM_BLO + off) = make_uint4(
            pkbf(bflo(v0.x), bflo(v0.y)), pkbf(bflo(v0.z), bflo(v0.w)),
            pkbf(bflo(v1.x), bflo(v1.y)), pkbf(bflo(v1.z), bflo(v1.w)));
    }
    if (tid < H) { ssum[tid] = 0.f; ssq[tid] = 0.f; }
    __syncthreads();

    const int wm = wid & 1, wn = wid >> 1;
    const int rbase = wm << 5, nbase = wn << 5;
    const int l7 = lane & 7, kp = lane >> 4, l15 = lane & 15;
    const int g = lane >> 2, tq = lane & 3;
    const uint32_t aRowHi = sb + MM_AHI + (uint32_t)(rbase + l15) * 512;
    const uint32_t aRowLo = aRowHi + (MM_ALO - MM_AHI);
    const int nb0 = (nbase >> 3) + kp;
    const uint32_t bch0 = (uint32_t)((nb0 ^ l7) << 4);
    const uint32_t bch1 = (uint32_t)(((nb0 + 2) ^ l7) << 4);
    const uint32_t bHiBase = sb + MM_BHI + (uint32_t)l15 * 256;
    const uint32_t bLoBase = sb + MM_BLO + (uint32_t)l15 * 256;

    const int srow = tid >> 2, skq = (tid & 3) << 6;
    const bool selfHalf = skq < 128;
    float csum[8], csq[8];
    #pragma unroll
    for (int i = 0; i < 8; ++i) { csum[i] = 0.f; csq[i] = 0.f; }

    for (int t = blockIdx.x; t < T64; t += gridDim.x) {
        int t0 = t << 6;
        __syncthreads();
        // ---- stage A tile hi/lo ----
        {
            int rowg = t0 + srow;
            bool valid = rowg < NDV;
            float iv = (valid && !selfHalf) ? g_inv[rowg] : 1.f;
            const float* srcp = selfHalf ? (A + (size_t)rowg * H + skq)
                                         : (g_agg + (size_t)rowg * H + (skq - 128));
            uint32_t rowoff = (uint32_t)srow * 512;
            int rs = srow & 7;
            #pragma unroll
            for (int j = 0; j < 16; ++j) {
                float4 v = valid ? *(const float4*)(srcp + (j << 2))
                                 : make_float4(0.f, 0.f, 0.f, 0.f);
                if (!selfHalf) { v.x *= iv; v.y *= iv; v.z *= iv; v.w *= iv; }
                int k = skq + (j << 2);
                uint32_t off = rowoff + (uint32_t)(((k >> 3) ^ rs) << 4) + (uint32_t)((k & 7) << 1);
                *(uint2*)(smem + MM_AHI + off) = make_uint2(pkbf(v.x, v.y), pkbf(v.z, v.w));
                *(uint2*)(smem + MM_ALO + off) = make_uint2(pkbf(bflo(v.x), bflo(v.y)),
                                                            pkbf(bflo(v.z), bflo(v.w)));
            }
        }
        __syncthreads();

        float d[2][4][4];
        #pragma unroll
        for (int m = 0; m < 2; ++m)
            #pragma unroll
            for (int nb = 0; nb < 4; ++nb)
                #pragma unroll
                for (int e = 0; e < 4; ++e) d[m][nb][e] = 0.f;

        #pragma unroll 4
        for (int ks = 0; ks < 16; ++ks) {
            uint32_t ach = (uint32_t)((((ks << 1) + kp) ^ l7) << 4);
            uint32_t ahi0[4], ahi1[4], alo0[4], alo1[4];
            ldmA(ahi0, aRowHi + ach);
            ldmA(ahi1, aRowHi + 8192 + ach);
            ldmA(alo0, aRowLo + ach);
            ldmA(alo1, aRowLo + 8192 + ach);
            uint32_t bks = (uint32_t)ks << 12;
            uint32_t bh0[4], bh1[4], bl0[4], bl1[4];
            ldmBT(bh0, bHiBase + bks + bch0);
            ldmBT(bh1, bHiBase + bks + bch1);
            ldmBT(bl0, bLoBase + bks + bch0);
            ldmBT(bl1, bLoBase + bks + bch1);
            mmabf(d[0][0], ahi0, bh0); mmabf(d[0][1], ahi0, bh0 + 2);
            mmabf(d[0][2], ahi0, bh1); mmabf(d[0][3], ahi0, bh1 + 2);
            mmabf(d[1][0], ahi1, bh0); mmabf(d[1][1], ahi1, bh0 + 2);
            mmabf(d[1][2], ahi1, bh1); mmabf(d[1][3], ahi1, bh1 + 2);
            mmabf(d[0][0], ahi0, bl0); mmabf(d[0][1], ahi0, bl0 + 2);
            mmabf(d[0][2], ahi0, bl1); mmabf(d[0][3], ahi0, bl1 + 2);
            mmabf(d[1][0], ahi1, bl0); mmabf(d[1][1], ahi1, bl0 + 2);
            mmabf(d[1][2], ahi1, bl1); mmabf(d[1][3], ahi1, bl1 + 2);
            mmabf(d[0][0], alo0, bh0); mmabf(d[0][1], alo0, bh0 + 2);
            mmabf(d[0][2], alo0, bh1); mmabf(d[0][3], alo0, bh1 + 2);
            mmabf(d[1][0], alo1, bh0); mmabf(d[1][1], alo1, bh0 + 2);
            mmabf(d[1][2], alo1, bh1); mmabf(d[1][3], alo1, bh1 + 2);
        }

        // ---- epilogue + BN partials ----
        #pragma unroll
        for (int m = 0; m < 2; ++m) {
            int row0 = t0 + rbase + (m << 4) + g;
            int row1 = row0 + 8;
            if (row0 < NDV) {
                float* o = g_out + (size_t)row0 * H + nbase + (tq << 1);
                #pragma unroll
                for (int nb = 0; nb < 4; ++nb) {
                    *(float2*)(o + (nb << 3)) = make_float2(d[m][nb][0], d[m][nb][1]);
                    csum[nb * 2 + 0] += d[m][nb][0]; csq[nb * 2 + 0] += d[m][nb][0] * d[m][nb][0];
                    csum[nb * 2 + 1] += d[m][nb][1]; csq[nb * 2 + 1] += d[m][nb][1] * d[m][nb][1];
                }
            }
            if (row1 < NDV) {
                float* o = g_out + (size_t)row1 * H + nbase + (tq << 1);
                #pragma unroll
                for (int nb = 0; nb < 4; ++nb) {
                    *(float2*)(o + (nb << 3)) = make_float2(d[m][nb][2], d[m][nb][3]);
                    csum[nb * 2 + 0] += d[m][nb][2]; csq[nb * 2 + 0] += d[m][nb][2] * d[m][nb][2];
                    csum[nb * 2 + 1] += d[m][nb][3]; csq[nb * 2 + 1] += d[m][nb][3] * d[m][nb][3];
                }
            }
        }
    }

    #pragma unroll
    for (int nb = 0; nb < 4; ++nb)
        #pragma unroll
        for (int j = 0; j < 2; ++j) {
            int col = nbase + (tq << 1) + (nb << 3) + j;
            atomicAdd(&ssum[col], csum[nb * 2 + j]);
            atomicAdd(&ssq[col],  csq[nb * 2 + j]);
        }
    __syncthreads();
    if (tid < H) {
        atomicAdd(&g_sum[tid], ssum[tid]);
        atomicAdd(&g_sq[tid],  ssq[tid]);
    }
}

// consumes stats AND re-zeroes them (replay-invariant)
__global__ void k_bnfin(const float* __restrict__ gamma, const float* __restrict__ beta) {
    int c = threadIdx.x;
    float mean = g_sum[c] * (1.f / NDV);
    float var  = g_sq[c]  * (1.f / NDV) - mean * mean;
    float sc = gamma[c] * rsqrtf(var + 1e-5f);
    g_scale[c] = sc;
    g_shift[c] = beta[c] - mean * sc;
    g_sum[c] = 0.f;
    g_sq[c]  = 0.f;
}

// once-per-node BN+ReLU: g_h = relu(g_out*scale+shift)
__global__ void k_apply() {
    int i = blockIdx.x * blockDim.x + threadIdx.x;
    if (i >= NDV * 32) return;
    int c4 = i & 31;
    float4 v  = ((const float4*)g_out)[i];
    float4 sc = ((const float4*)g_scale)[c4];
    float4 sh = ((const float4*)g_shift)[c4];
    v.x = fmaxf(fmaf(v.x, sc.x, sh.x), 0.f);
    v.y = fmaxf(fmaf(v.y, sc.y, sh.y), 0.f);
    v.z = fmaxf(fmaf(v.z, sc.z, sh.z), 0.f);
    v.w = fmaxf(fmaf(v.w, sc.w, sh.w), 0.f);
    ((float4*)g_h)[i] = v;
}

// ---------------- layer 2 GEMM (FFMA2) -----------------------------------------
#define TILES64 ((NDV + 63) / 64)
#define SMEM2 ((128 * 128 + 128 * 64) * 4)

__global__ __launch_bounds__(256, 1)
void k_gemm2(const float* __restrict__ Wself, const float* __restrict__ Wneigh,
             const float* __restrict__ bias, float* __restrict__ out) {
    extern __shared__ float sm[];
    float* Bs = sm;
    float* As = sm + 128 * 128;
    int tid = threadIdx.x;

    for (int i = tid; i < 128 * 128 / 4; i += 256) {
        int e = i * 4, k = e >> 7, c = e & 127;
        float4 v = make_float4(0.f, 0.f, 0.f, 0.f);
        if (c < 40)      v = *(const float4*)(Wself  + k * OD + c);
        else if (c < 80) v = *(const float4*)(Wneigh + k * OD + (c - 40));
        *(float4*)(Bs + e) = v;
    }
    __syncthreads();

    const int r = tid & 63, c0 = tid >> 6;
    const int w = tid >> 5, lane = tid & 31;
    const int r0 = w << 3, cc = lane << 2;

    for (int t = blockIdx.x; t < TILES64; t += gridDim.x) {
        int t0 = t * 64;
        __syncthreads();
        {
            int row = t0 + r;
            bool valid = row < NDV;
            const float* arow = (const float*)g_h + (size_t)row * H;
            #pragma unroll
            for (int j = 0; j < 8; ++j) {
                int k = (c0 + (j << 2)) << 2;
                float4 v = valid ? *(const float4*)(arow + k) : make_float4(0.f, 0.f, 0.f, 0.f);
                float* p = As + k * 64 + r;
                p[0] = v.x; p[64] = v.y; p[128] = v.z; p[192] = v.w;
            }
        }
        __syncthreads();

        unsigned long long acc[4][4];
        #pragma unroll
        for (int p = 0; p < 4; p++)
            #pragma unroll
            for (int c = 0; c < 4; c++) acc[p][c] = 0ull;

        #pragma unroll 8
        for (int k = 0; k < 128; ++k) {
            float4 alo = *(const float4*)(As + k * 64 + r0);
            float4 ahi = *(const float4*)(As + k * 64 + r0 + 4);
            float4 bv  = *(const float4*)(Bs + k * 128 + cc);
            unsigned long long a0 = pk2(alo.x, alo.y), a1 = pk2(alo.z, alo.w);
            unsigned long long a2 = pk2(ahi.x, ahi.y), a3 = pk2(ahi.z, ahi.w);
            unsigned long long b0 = pk2(bv.x, bv.x), b1 = pk2(bv.y, bv.y);
            unsigned long long b2 = pk2(bv.z, bv.z), b3 = pk2(bv.w, bv.w);
            fma2(acc[0][0], a0, b0); fma2(acc[0][1], a0, b1);
            fma2(acc[0][2], a0, b2); fma2(acc[0][3], a0, b3);
            fma2(acc[1][0], a1, b0); fma2(acc[1][1], a1, b1);
            fma2(acc[1][2], a1, b2); fma2(acc[1][3], a1, b3);
            fma2(acc[2][0], a2, b0); fma2(acc[2][1], a2, b1);
            fma2(acc[2][2], a2, b2); fma2(acc[2][3], a2, b3);
            fma2(acc[3][0], a3, b0); fma2(acc[3][1], a3, b1);
            fma2(acc[3][2], a3, b2); fma2(acc[3][3], a3, b3);
        }

        #pragma unroll
        for (int p = 0; p < 4; p++) {
            float va[4], vb[4];
            #pragma unroll
            for (int c = 0; c < 4; c++) upk2(acc[p][c], va[c], vb[c]);
            int rowA = t0 + r0 + 2 * p, rowB = rowA + 1;
            if (rowA < NDV) {
                #pragma unroll
                for (int c = 0; c < 4; c++) {
                    int col = cc + c;
                    if (col < 40)      out[(size_t)rowA * OD + col] = va[c] + bias[col];
                    else if (col < 80) g_p[(size_t)rowA * OD + col - 40] = va[c];
                }
            }
            if (rowB < NDV) {
                #pragma unroll
                for (int c = 0; c < 4; c++) {
                    int col = cc + c;
                    if (col < 40)      out[(size_t)rowB * OD + col] = vb[c] + bias[col];
                    else if (col < 80) g_p[(size_t)rowB * OD + col - 40] = vb[c];
                }
            }
        }
    }
}

// out[dst] += p[src] * inv_deg[dst]
__global__ void k_edge2(const int* __restrict__ src, const int* __restrict__ dst,
                        float* __restrict__ out) {
    int idx = blockIdx.x * blockDim.x + threadIdx.x;
    if (idx >= NE * 10) return;
    int e = idx / 10, c4 = idx - e * 10;
    int s = src[e], d = dst[e];
    float iv = g_inv[d];
    float4 v = *(const float4*)(g_p + (size_t)s * OD + c4 * 4);
    float* o = out + (size_t)d * OD + c4 * 4;
    red4(o, v.x * iv, v.y * iv, v.z * iv, v.w * iv);
}

// ---------------- host launcher ------------------------------------------------
extern "C" void kernel_launch(void* const* d_in, const int* in_sizes, int n_in,
                              void* d_out, int out_size) {
    const float* feat = (const float*)d_in[0];
    const int*   src  = (const int*)d_in[1];
    const int*   dst  = (const int*)d_in[2];
    const float* Ws0 = (const float*)d_in[3];
    const float* Wn0 = (const float*)d_in[4];
    const float* ga0 = (const float*)d_in[5];
    const float* be0 = (const float*)d_in[6];
    const float* Ws1 = (const float*)d_in[7];
    const float* Wn1 = (const float*)d_in[8];
    const float* ga1 = (const float*)d_in[9];
    const float* be1 = (const float*)d_in[10];
    const float* Ws2 = (const float*)d_in[11];
    const float* Wn2 = (const float*)d_in[12];
    const float* b2  = (const float*)d_in[13];
    float* out = (float*)d_out;

    cudaFuncSetAttribute(k_gemm01mma, cudaFuncAttributeMaxDynamicSharedMemorySize, MM_TOT);
    cudaFuncSetAttribute(k_gemm2,     cudaFuncAttributeMaxDynamicSharedMemorySize, SMEM2);

    const int TB = 256;
    k_zero_deg<<<(NDV + TB - 1) / TB, TB>>>();
    k_deg<<<(NE + TB - 1) / TB, TB>>>(dst);
    k_inv<<<(NDV + TB - 1) / TB, TB>>>();

    // ---- layer 0 ----
    k_zero_agg<<<(NDV * H / 4 + TB - 1) / TB, TB>>>();
    k_agg<<<((size_t)NE * 32 + TB - 1) / TB, TB>>>(src, dst, feat, 0);
    k_gemm01mma<<<148, 256, MM_TOT>>>(feat, 0, Ws0, Wn0);
    k_bnfin<<<1, 128>>>(ga0, be0);
    k_apply<<<(NDV * 32 + TB - 1) / TB, TB>>>();

    // ---- layer 1 ----
    k_zero_agg<<<(NDV * H / 4 + TB - 1) / TB, TB>>>();
    k_agg<<<((size_t)NE * 32 + TB - 1) / TB, TB>>>(src, dst, nullptr, 1);
    k_gemm01mma<<<148, 256, MM_TOT>>>(nullptr, 1, Ws1, Wn1);
    k_bnfin<<<1, 128>>>(ga1, be1);
    k_apply<<<(NDV * 32 + TB - 1) / TB, TB>>>();

    // ---- layer 2 ----
    k_gemm2<<<148, 256, SMEM2>>>(Ws2, Wn2, b2, out);
    k_edge2<<<((size_t)NE * 10 + TB - 1) / TB, TB>>>(src, dst, out);

    (void)in_sizes; (void)n_in; (void)out_size;
}

// round 8
// speedup vs baseline: 1.2119x; 1.0942x over previous
#include <cuda_runtime.h>
#include <cuda_bf16.h>
#include <cstdint>

#define NDV 100000
#define NE  800000
#define H   128
#define OD  40

// ---------------- device scratch (static globals: allocation-free) -------------
__device__ float g_agg[(size_t)NDV * H];
__device__ float g_out[(size_t)NDV * H];
__device__ float g_h  [(size_t)NDV * H];
__device__ float g_p  [(size_t)NDV * OD];
__device__ float g_deg[NDV];
__device__ float g_inv[NDV];
__device__ float g_sum[H];      // zero at load; k_bnfin re-zeroes after consuming
__device__ float g_sq [H];
__device__ float g_scale[H];
__device__ float g_shift[H];

// ---------------- helpers ------------------------------------------------------
__device__ __forceinline__ uint32_t s2u(const void* p) {
    uint32_t a;
    asm("{ .reg .u64 t; cvta.to.shared.u64 t, %1; cvt.u32.u64 %0, t; }" : "=r"(a) : "l"(p));
    return a;
}
__device__ __forceinline__ void red4(float* p, float x, float y, float z, float w) {
    asm volatile("red.global.add.v4.f32 [%0], {%1,%2,%3,%4};"
                 :: "l"(p), "f"(x), "f"(y), "f"(z), "f"(w) : "memory");
}
__device__ __forceinline__ uint32_t pkbf(float a, float b) {
    __nv_bfloat162 t = __halves2bfloat162(__float2bfloat16(a), __float2bfloat16(b));
    return *(uint32_t*)&t;
}
__device__ __forceinline__ float bflo(float x) {
    __nv_bfloat16 h = __float2bfloat16(x);
    return x - __bfloat162float(h);
}
__device__ __forceinline__ void ldmA(uint32_t* r, uint32_t a) {
    asm volatile("ldmatrix.sync.aligned.m8n8.x4.shared.b16 {%0,%1,%2,%3},[%4];"
                 : "=r"(r[0]), "=r"(r[1]), "=r"(r[2]), "=r"(r[3]) : "r"(a));
}
__device__ __forceinline__ void ldmBT(uint32_t* r, uint32_t a) {
    asm volatile("ldmatrix.sync.aligned.m8n8.x4.trans.shared.b16 {%0,%1,%2,%3},[%4];"
                 : "=r"(r[0]), "=r"(r[1]), "=r"(r[2]), "=r"(r[3]) : "r"(a));
}
__device__ __forceinline__ void mmabf(float* d, const uint32_t* a, const uint32_t* b) {
    asm volatile("mma.sync.aligned.m16n8k16.row.col.f32.bf16.bf16.f32 "
                 "{%0,%1,%2,%3},{%4,%5,%6,%7},{%8,%9},{%0,%1,%2,%3};"
                 : "+f"(d[0]), "+f"(d[1]), "+f"(d[2]), "+f"(d[3])
                 : "r"(a[0]), "r"(a[1]), "r"(a[2]), "r"(a[3]), "r"(b[0]), "r"(b[1]));
}

// ---------------- small kernels ------------------------------------------------
__global__ void k_zero_deg() {
    int i = blockIdx.x * blockDim.x + threadIdx.x;
    if (i < NDV) g_deg[i] = 0.f;
}
__global__ void k_zero_agg() {
    int i = blockIdx.x * blockDim.x + threadIdx.x;
    if (i < NDV * H / 4) ((float4*)g_agg)[i] = make_float4(0.f, 0.f, 0.f, 0.f);
}
__global__ void k_deg(const int* __restrict__ dst) {
    int e = blockIdx.x * blockDim.x + threadIdx.x;
    if (e < NE) atomicAdd(&g_deg[dst[e]], 1.f);
}
__global__ void k_inv() {
    int i = blockIdx.x * blockDim.x + threadIdx.x;
    if (i < NDV) g_inv[i] = 1.f / fmaxf(g_deg[i], 1.f);
}

// warp-per-edge gather + vector red scatter
__global__ void k_agg(const int* __restrict__ src, const int* __restrict__ dst,
                      const float* __restrict__ hext, int use_gh) {
    int idx = blockIdx.x * blockDim.x + threadIdx.x;
    int e = idx >> 5, lane = idx & 31;
    if (e >= NE) return;
    const float* h = use_gh ? (const float*)g_h : hext;
    int s = src[e], d = dst[e];
    float4 v = ((const float4*)(h + (size_t)s * H))[lane];
    float* o = g_agg + (size_t)d * H + lane * 4;
    red4(o, v.x, v.y, v.z, v.w);
}

// ================= layers 0/1 GEMM via mma.sync bf16 (3-term split) ============
#define T64 ((NDV + 63) >> 6)
#define MM_BHI 0
#define MM_BLO 65536
#define MM_AHI 131072
#define MM_ALO 163840
#define MM_STAT 196608
#define MM_TOT (196608 + 1024)

__global__ __launch_bounds__(256, 1)
void k_gemm01mma(const float* __restrict__ Aext, int use_gh,
                 const float* __restrict__ Wself, const float* __restrict__ Wneigh) {
    extern __shared__ char smem[];
    uint32_t sb = s2u(smem);
    float* ssum = (float*)(smem + MM_STAT);
    float* ssq  = ssum + H;
    const int tid = threadIdx.x, lane = tid & 31, wid = tid >> 5;
    const float* A = use_gh ? (const float*)g_h : Aext;

    for (int it = 0; it < 16; ++it) {
        int idx = tid + (it << 8);
        int k = idx >> 4, nc = idx & 15, n0 = nc << 3;
        const float* wsrc = (k < 128) ? (Wself + k * H + n0) : (Wneigh + (k - 128) * H + n0);
        float4 v0 = *(const float4*)(wsrc);
        float4 v1 = *(const float4*)(wsrc + 4);
        uint32_t off = (uint32_t)k * 256 + (uint32_t)((nc ^ (k & 7)) << 4);
        *(uint4*)(smem + MM_BHI + off) = make_uint4(
            pkbf(v0.x, v0.y), pkbf(v0.z, v0.w), pkbf(v1.x, v1.y), pkbf(v1.z, v1.w));
        *(uint4*)(smem + MM_BLO + off) = make_uint4(
            pkbf(bflo(v0.x), bflo(v0.y)), pkbf(bflo(v0.z), bflo(v0.w)),
            pkbf(bflo(v1.x), bflo(v1.y)), pkbf(bflo(v1.z), bflo(v1.w)));
    }
    if (tid < H) { ssum[tid] = 0.f; ssq[tid] = 0.f; }
    __syncthreads();

    const int wm = wid & 1, wn = wid >> 1;
    const int rbase = wm << 5, nbase = wn << 5;
    const int l7 = lane & 7, kp = lane >> 4, l15 = lane & 15;
    const int g = lane >> 2, tq = lane & 3;
    const uint32_t aRowHi = sb + MM_AHI + (uint32_t)(rbase + l15) * 512;
    const uint32_t aRowLo = aRowHi + (MM_ALO - MM_AHI);
    const int nb0 = (nbase >> 3) + kp;
    const uint32_t bch0 = (uint32_t)((nb0 ^ l7) << 4);
    const uint32_t bch1 = (uint32_t)(((nb0 + 2) ^ l7) << 4);
    const uint32_t bHiBase = sb + MM_BHI + (uint32_t)l15 * 256;
    const uint32_t bLoBase = sb + MM_BLO + (uint32_t)l15 * 256;

    const int srow = tid >> 2, skq = (tid & 3) << 6;
    const bool selfHalf = skq < 128;
    float csum[8], csq[8];
    #pragma unroll
    for (int i = 0; i < 8; ++i) { csum[i] = 0.f; csq[i] = 0.f; }

    for (int t = blockIdx.x; t < T64; t += gridDim.x) {
        int t0 = t << 6;
        __syncthreads();
        {
            int rowg = t0 + srow;
            bool valid = rowg < NDV;
            float iv = (valid && !selfHalf) ? g_inv[rowg] : 1.f;
            const float* srcp = selfHalf ? (A + (size_t)rowg * H + skq)
                                         : (g_agg + (size_t)rowg * H + (skq - 128));
            uint32_t rowoff = (uint32_t)srow * 512;
            int rs = srow & 7;
            #pragma unroll
            for (int j = 0; j < 16; ++j) {
                float4 v = valid ? *(const float4*)(srcp + (j << 2))
                                 : make_float4(0.f, 0.f, 0.f, 0.f);
                if (!selfHalf) { v.x *= iv; v.y *= iv; v.z *= iv; v.w *= iv; }
                int k = skq + (j << 2);
                uint32_t off = rowoff + (uint32_t)(((k >> 3) ^ rs) << 4) + (uint32_t)((k & 7) << 1);
                *(uint2*)(smem + MM_AHI + off) = make_uint2(pkbf(v.x, v.y), pkbf(v.z, v.w));
                *(uint2*)(smem + MM_ALO + off) = make_uint2(pkbf(bflo(v.x), bflo(v.y)),
                                                            pkbf(bflo(v.z), bflo(v.w)));
            }
        }
        __syncthreads();

        float d[2][4][4];
        #pragma unroll
        for (int m = 0; m < 2; ++m)
            #pragma unroll
            for (int nb = 0; nb < 4; ++nb)
                #pragma unroll
                for (int e = 0; e < 4; ++e) d[m][nb][e] = 0.f;

        #pragma unroll 4
        for (int ks = 0; ks < 16; ++ks) {
            uint32_t ach = (uint32_t)((((ks << 1) + kp) ^ l7) << 4);
            uint32_t ahi0[4], ahi1[4], alo0[4], alo1[4];
            ldmA(ahi0, aRowHi + ach);
            ldmA(ahi1, aRowHi + 8192 + ach);
            ldmA(alo0, aRowLo + ach);
            ldmA(alo1, aRowLo + 8192 + ach);
            uint32_t bks = (uint32_t)ks << 12;
            uint32_t bh0[4], bh1[4], bl0[4], bl1[4];
            ldmBT(bh0, bHiBase + bks + bch0);
            ldmBT(bh1, bHiBase + bks + bch1);
            ldmBT(bl0, bLoBase + bks + bch0);
            ldmBT(bl1, bLoBase + bks + bch1);
            mmabf(d[0][0], ahi0, bh0); mmabf(d[0][1], ahi0, bh0 + 2);
            mmabf(d[0][2], ahi0, bh1); mmabf(d[0][3], ahi0, bh1 + 2);
            mmabf(d[1][0], ahi1, bh0); mmabf(d[1][1], ahi1, bh0 + 2);
            mmabf(d[1][2], ahi1, bh1); mmabf(d[1][3], ahi1, bh1 + 2);
            mmabf(d[0][0], ahi0, bl0); mmabf(d[0][1], ahi0, bl0 + 2);
            mmabf(d[0][2], ahi0, bl1); mmabf(d[0][3], ahi0, bl1 + 2);
            mmabf(d[1][0], ahi1, bl0); mmabf(d[1][1], ahi1, bl0 + 2);
            mmabf(d[1][2], ahi1, bl1); mmabf(d[1][3], ahi1, bl1 + 2);
            mmabf(d[0][0], alo0, bh0); mmabf(d[0][1], alo0, bh0 + 2);
            mmabf(d[0][2], alo0, bh1); mmabf(d[0][3], alo0, bh1 + 2);
            mmabf(d[1][0], alo1, bh0); mmabf(d[1][1], alo1, bh0 + 2);
            mmabf(d[1][2], alo1, bh1); mmabf(d[1][3], alo1, bh1 + 2);
        }

        #pragma unroll
        for (int m = 0; m < 2; ++m) {
            int row0 = t0 + rbase + (m << 4) + g;
            int row1 = row0 + 8;
            if (row0 < NDV) {
                float* o = g_out + (size_t)row0 * H + nbase + (tq << 1);
                #pragma unroll
                for (int nb = 0; nb < 4; ++nb) {
                    *(float2*)(o + (nb << 3)) = make_float2(d[m][nb][0], d[m][nb][1]);
                    csum[nb * 2 + 0] += d[m][nb][0]; csq[nb * 2 + 0] += d[m][nb][0] * d[m][nb][0];
                    csum[nb * 2 + 1] += d[m][nb][1]; csq[nb * 2 + 1] += d[m][nb][1] * d[m][nb][1];
                }
            }
            if (row1 < NDV) {
                float* o = g_out + (size_t)row1 * H + nbase + (tq << 1);
                #pragma unroll
                for (int nb = 0; nb < 4; ++nb) {
                    *(float2*)(o + (nb << 3)) = make_float2(d[m][nb][2], d[m][nb][3]);
                    csum[nb * 2 + 0] += d[m][nb][2]; csq[nb * 2 + 0] += d[m][nb][2] * d[m][nb][2];
                    csum[nb * 2 + 1] += d[m][nb][3]; csq[nb * 2 + 1] += d[m][nb][3] * d[m][nb][3];
                }
            }
        }
    }

    #pragma unroll
    for (int nb = 0; nb < 4; ++nb)
        #pragma unroll
        for (int j = 0; j < 2; ++j) {
            int col = nbase + (tq << 1) + (nb << 3) + j;
            atomicAdd(&ssum[col], csum[nb * 2 + j]);
            atomicAdd(&ssq[col],  csq[nb * 2 + j]);
        }
    __syncthreads();
    if (tid < H) {
        atomicAdd(&g_sum[tid], ssum[tid]);
        atomicAdd(&g_sq[tid],  ssq[tid]);
    }
}

// consumes stats AND re-zeroes them (replay-invariant)
__global__ void k_bnfin(const float* __restrict__ gamma, const float* __restrict__ beta) {
    int c = threadIdx.x;
    float mean = g_sum[c] * (1.f / NDV);
    float var  = g_sq[c]  * (1.f / NDV) - mean * mean;
    float sc = gamma[c] * rsqrtf(var + 1e-5f);
    g_scale[c] = sc;
    g_shift[c] = beta[c] - mean * sc;
    g_sum[c] = 0.f;
    g_sq[c]  = 0.f;
}

// once-per-node BN+ReLU: g_h = relu(g_out*scale+shift)
__global__ void k_apply() {
    int i = blockIdx.x * blockDim.x + threadIdx.x;
    if (i >= NDV * 32) return;
    int c4 = i & 31;
    float4 v  = ((const float4*)g_out)[i];
    float4 sc = ((const float4*)g_scale)[c4];
    float4 sh = ((const float4*)g_shift)[c4];
    v.x = fmaxf(fmaf(v.x, sc.x, sh.x), 0.f);
    v.y = fmaxf(fmaf(v.y, sc.y, sh.y), 0.f);
    v.z = fmaxf(fmaf(v.z, sc.z, sh.z), 0.f);
    v.w = fmaxf(fmaf(v.w, sc.w, sh.w), 0.f);
    ((float4*)g_h)[i] = v;
}

// ================= layer 2 GEMM via mma.sync bf16 (3-term split) ===============
// D[64,128pad] = g_h[64,128] @ [Ws2 | Wn2 | 0]; cols 0..39 -> out(+bias), 40..79 -> g_p
#define M2_BHI 0
#define M2_BLO 32768
#define M2_AHI 65536
#define M2_ALO 81920
#define M2_TOT 98304

__global__ __launch_bounds__(256, 1)
void k_gemm2mma(const float* __restrict__ Wself, const float* __restrict__ Wneigh,
                const float* __restrict__ bias, float* __restrict__ out) {
    extern __shared__ char smem[];
    uint32_t sb = s2u(smem);
    const int tid = threadIdx.x, lane = tid & 31, wid = tid >> 5;

    // ---- stage B hi/lo: [k=128][n=128pad], 256B rows, chunk ^= (k&7) ----
    for (int it = 0; it < 8; ++it) {
        int idx = tid + (it << 8);          // 0..2047 chunks of 8 floats
        int k = idx >> 4, nc = idx & 15, n0 = nc << 3;
        float4 v0 = make_float4(0.f, 0.f, 0.f, 0.f), v1 = v0;
        if (n0 < 40) {
            const float* w = Wself + k * OD + n0;
            v0 = *(const float4*)(w); v1 = *(const float4*)(w + 4);
        } else if (n0 < 80) {
            const float* w = Wneigh + k * OD + (n0 - 40);
            v0 = *(const float4*)(w); v1 = *(const float4*)(w + 4);
        }
        uint32_t off = (uint32_t)k * 256 + (uint32_t)((nc ^ (k & 7)) << 4);
        *(uint4*)(smem + M2_BHI + off) = make_uint4(
            pkbf(v0.x, v0.y), pkbf(v0.z, v0.w), pkbf(v1.x, v1.y), pkbf(v1.z, v1.w));
        *(uint4*)(smem + M2_BLO + off) = make_uint4(
            pkbf(bflo(v0.x), bflo(v0.y)), pkbf(bflo(v0.z), bflo(v0.w)),
            pkbf(bflo(v1.x), bflo(v1.y)), pkbf(bflo(v1.z), bflo(v1.w)));
    }
    __syncthreads();

    const int wm = wid & 1, wn = wid >> 1;
    const int rbase = wm << 5, nbase = wn << 5;
    const int l7 = lane & 7, kp = lane >> 4, l15 = lane & 15;
    const int g = lane >> 2, tq = lane & 3;
    const uint32_t aRowHi = sb + M2_AHI + (uint32_t)(rbase + l15) * 256;
    const uint32_t aRowLo = aRowHi + (M2_ALO - M2_AHI);
    const int nb0 = (nbase >> 3) + kp;
    const uint32_t bch0 = (uint32_t)((nb0 ^ l7) << 4);
    const uint32_t bch1 = (uint32_t)(((nb0 + 2) ^ l7) << 4);
    const uint32_t bHiBase = sb + M2_BHI + (uint32_t)l15 * 256;
    const uint32_t bLoBase = sb + M2_BLO + (uint32_t)l15 * 256;

    const int srow = tid >> 2, skq = (tid & 3) << 5;   // 32 k per thread

    for (int t = blockIdx.x; t < T64; t += gridDim.x) {
        int t0 = t << 6;
        __syncthreads();
        // ---- stage A (g_h) hi/lo: [row=64][k=128], 256B rows ----
        {
            int rowg = t0 + srow;
            bool valid = rowg < NDV;
            const float* srcp = (const float*)g_h + (size_t)rowg * H + skq;
            uint32_t rowoff = (uint32_t)srow * 256;
            int rs = srow & 7;
            #pragma unroll
            for (int j = 0; j < 8; ++j) {
                float4 v = valid ? *(const float4*)(srcp + (j << 2))
                                 : make_float4(0.f, 0.f, 0.f, 0.f);
                int k = skq + (j << 2);
                uint32_t off = rowoff + (uint32_t)(((k >> 3) ^ rs) << 4) + (uint32_t)((k & 7) << 1);
                *(uint2*)(smem + M2_AHI + off) = make_uint2(pkbf(v.x, v.y), pkbf(v.z, v.w));
                *(uint2*)(smem + M2_ALO + off) = make_uint2(pkbf(bflo(v.x), bflo(v.y)),
                                                            pkbf(bflo(v.z), bflo(v.w)));
            }
        }
        __syncthreads();

        float d[2][4][4];
        #pragma unroll
        for (int m = 0; m < 2; ++m)
            #pragma unroll
            for (int nb = 0; nb < 4; ++nb)
                #pragma unroll
                for (int e = 0; e < 4; ++e) d[m][nb][e] = 0.f;

        #pragma unroll 4
        for (int ks = 0; ks < 8; ++ks) {
            uint32_t ach = (uint32_t)((((ks << 1) + kp) ^ l7) << 4);
            uint32_t ahi0[4], ahi1[4], alo0[4], alo1[4];
            ldmA(ahi0, aRowHi + ach);
            ldmA(ahi1, aRowHi + 4096 + ach);
            ldmA(alo0, aRowLo + ach);
            ldmA(alo1, aRowLo + 4096 + ach);
            uint32_t bks = (uint32_t)ks << 12;
            uint32_t bh0[4], bh1[4], bl0[4], bl1[4];
            ldmBT(bh0, bHiBase + bks + bch0);
            ldmBT(bh1, bHiBase + bks + bch1);
            ldmBT(bl0, bLoBase + bks + bch0);
            ldmBT(bl1, bLoBase + bks + bch1);
            mmabf(d[0][0], ahi0, bh0); mmabf(d[0][1], ahi0, bh0 + 2);
            mmabf(d[0][2], ahi0, bh1); mmabf(d[0][3], ahi0, bh1 + 2);
            mmabf(d[1][0], ahi1, bh0); mmabf(d[1][1], ahi1, bh0 + 2);
            mmabf(d[1][2], ahi1, bh1); mmabf(d[1][3], ahi1, bh1 + 2);
            mmabf(d[0][0], ahi0, bl0); mmabf(d[0][1], ahi0, bl0 + 2);
            mmabf(d[0][2], ahi0, bl1); mmabf(d[0][3], ahi0, bl1 + 2);
            mmabf(d[1][0], ahi1, bl0); mmabf(d[1][1], ahi1, bl0 + 2);
            mmabf(d[1][2], ahi1, bl1); mmabf(d[1][3], ahi1, bl1 + 2);
            mmabf(d[0][0], alo0, bh0); mmabf(d[0][1], alo0, bh0 + 2);
            mmabf(d[0][2], alo0, bh1); mmabf(d[0][3], alo0, bh1 + 2);
            mmabf(d[1][0], alo1, bh0); mmabf(d[1][1], alo1, bh0 + 2);
            mmabf(d[1][2], alo1, bh1); mmabf(d[1][3], alo1, bh1 + 2);
        }

        // ---- epilogue: cols<40 -> out(+bias); 40..79 -> g_p ----
        #pragma unroll
        for (int m = 0; m < 2; ++m) {
            int row0 = t0 + rbase + (m << 4) + g;
            int row1 = row0 + 8;
            #pragma unroll
            for (int nb = 0; nb < 4; ++nb) {
                int col = nbase + (tq << 1) + (nb << 3);
                #pragma unroll
                for (int j = 0; j < 2; ++j) {
                    int c = col + j;
                    if (c < 40) {
                        if (row0 < NDV) out[(size_t)row0 * OD + c] = d[m][nb][j] + bias[c];
                        if (row1 < NDV) out[(size_t)row1 * OD + c] = d[m][nb][j + 2] + bias[c];
                    } else if (c < 80) {
                        if (row0 < NDV) g_p[(size_t)row0 * OD + c - 40] = d[m][nb][j];
                        if (row1 < NDV) g_p[(size_t)row1 * OD + c - 40] = d[m][nb][j + 2];
                    }
                }
            }
        }
    }
}

// out[dst] += p[src] * inv_deg[dst]
__global__ void k_edge2(const int* __restrict__ src, const int* __restrict__ dst,
                        float* __restrict__ out) {
    int idx = blockIdx.x * blockDim.x + threadIdx.x;
    if (idx >= NE * 10) return;
    int e = idx / 10, c4 = idx - e * 10;
    int s = src[e], d = dst[e];
    float iv = g_inv[d];
    float4 v = *(const float4*)(g_p + (size_t)s * OD + c4 * 4);
    float* o = out + (size_t)d * OD + c4 * 4;
    red4(o, v.x * iv, v.y * iv, v.z * iv, v.w * iv);
}

// ---------------- host launcher ------------------------------------------------
extern "C" void kernel_launch(void* const* d_in, const int* in_sizes, int n_in,
                              void* d_out, int out_size) {
    const float* feat = (const float*)d_in[0];
    const int*   src  = (const int*)d_in[1];
    const int*   dst  = (const int*)d_in[2];
    const float* Ws0 = (const float*)d_in[3];
    const float* Wn0 = (const float*)d_in[4];
    const float* ga0 = (const float*)d_in[5];
    const float* be0 = (const float*)d_in[6];
    const float* Ws1 = (const float*)d_in[7];
    const float* Wn1 = (const float*)d_in[8];
    const float* ga1 = (const float*)d_in[9];
    const float* be1 = (const float*)d_in[10];
    const float* Ws2 = (const float*)d_in[11];
    const float* Wn2 = (const float*)d_in[12];
    const float* b2  = (const float*)d_in[13];
    float* out = (float*)d_out;

    cudaFuncSetAttribute(k_gemm01mma, cudaFuncAttributeMaxDynamicSharedMemorySize, MM_TOT);
    cudaFuncSetAttribute(k_gemm2mma,  cudaFuncAttributeMaxDynamicSharedMemorySize, M2_TOT);

    const int TB = 256;
    // launch order puts k_agg in profiled slot #4 (agg needs only zero_agg;
    // inv needs deg and only feeds the GEMM)
    k_zero_deg<<<(NDV + TB - 1) / TB, TB>>>();                                  // 1
    k_zero_agg<<<(NDV * H / 4 + TB - 1) / TB, TB>>>();                          // 2
    k_deg<<<(NE + TB - 1) / TB, TB>>>(dst);                                     // 3
    k_agg<<<((size_t)NE * 32 + TB - 1) / TB, TB>>>(src, dst, feat, 0);          // 4 <- profiled
    k_inv<<<(NDV + TB - 1) / TB, TB>>>();                                       // 5
    k_gemm01mma<<<148, 256, MM_TOT>>>(feat, 0, Ws0, Wn0);
    k_bnfin<<<1, 128>>>(ga0, be0);
    k_apply<<<(NDV * 32 + TB - 1) / TB, TB>>>();

    // ---- layer 1 ----
    k_zero_agg<<<(NDV * H / 4 + TB - 1) / TB, TB>>>();
    k_agg<<<((size_t)NE * 32 + TB - 1) / TB, TB>>>(src, dst, nullptr, 1);
    k_gemm01mma<<<148, 256, MM_TOT>>>(nullptr, 1, Ws1, Wn1);
    k_bnfin<<<1, 128>>>(ga1, be1);
    k_apply<<<(NDV * 32 + TB - 1) / TB, TB>>>();

    // ---- layer 2 ----
    k_gemm2mma<<<148, 256, M2_TOT>>>(Ws2, Wn2, b2, out);
    k_edge2<<<((size_t)NE * 10 + TB - 1) / TB, TB>>>(src, dst, out);

    (void)in_sizes; (void)n_in; (void)out_size;
}

// round 10
// speedup vs baseline: 1.3481x; 1.1123x over previous
#include <cuda_runtime.h>
#include <cuda_bf16.h>
#include <cstdint>

#define NDV 100000
#define NE  800000
#define H   128
#define OD  40

// ---------------- device scratch (static globals: allocation-free) -------------
__device__ float g_agg[(size_t)NDV * H];
__device__ float g_out[(size_t)NDV * H];
__device__ float g_h  [(size_t)NDV * H];
__device__ float g_p  [(size_t)NDV * OD];
__device__ float g_deg[NDV];
__device__ float g_inv[NDV];
__device__ float g_sum[H];      // zero at load; k_bnfin re-zeroes after consuming
__device__ float g_sq [H];
__device__ float g_scale[H];
__device__ float g_shift[H];

// ---------------- helpers ------------------------------------------------------
__device__ __forceinline__ uint32_t s2u(const void* p) {
    uint32_t a;
    asm("{ .reg .u64 t; cvta.to.shared.u64 t, %1; cvt.u32.u64 %0, t; }" : "=r"(a) : "l"(p));
    return a;
}
__device__ __forceinline__ void red4(float* p, float x, float y, float z, float w) {
    asm volatile("red.global.add.v4.f32 [%0], {%1,%2,%3,%4};"
                 :: "l"(p), "f"(x), "f"(y), "f"(z), "f"(w) : "memory");
}
__device__ __forceinline__ uint32_t pkbf(float a, float b) {
    __nv_bfloat162 t = __halves2bfloat162(__float2bfloat16(a), __float2bfloat16(b));
    return *(uint32_t*)&t;
}
__device__ __forceinline__ float bflo(float x) {
    __nv_bfloat16 h = __float2bfloat16(x);
    return x - __bfloat162float(h);
}
__device__ __forceinline__ void ldmA(uint32_t* r, uint32_t a) {
    asm volatile("ldmatrix.sync.aligned.m8n8.x4.shared.b16 {%0,%1,%2,%3},[%4];"
                 : "=r"(r[0]), "=r"(r[1]), "=r"(r[2]), "=r"(r[3]) : "r"(a));
}
__device__ __forceinline__ void ldmBT(uint32_t* r, uint32_t a) {
    asm volatile("ldmatrix.sync.aligned.m8n8.x4.trans.shared.b16 {%0,%1,%2,%3},[%4];"
                 : "=r"(r[0]), "=r"(r[1]), "=r"(r[2]), "=r"(r[3]) : "r"(a));
}
__device__ __forceinline__ void mmabf(float* d, const uint32_t* a, const uint32_t* b) {
    asm volatile("mma.sync.aligned.m16n8k16.row.col.f32.bf16.bf16.f32 "
                 "{%0,%1,%2,%3},{%4,%5,%6,%7},{%8,%9},{%0,%1,%2,%3};"
                 : "+f"(d[0]), "+f"(d[1]), "+f"(d[2]), "+f"(d[3])
                 : "r"(a[0]), "r"(a[1]), "r"(a[2]), "r"(a[3]), "r"(b[0]), "r"(b[1]));
}

// ---------------- small kernels ------------------------------------------------
__global__ void k_zero_deg() {
    int i = blockIdx.x * blockDim.x + threadIdx.x;
    if (i < NDV) g_deg[i] = 0.f;
}
__global__ void k_zero_agg() {
    int i = blockIdx.x * blockDim.x + threadIdx.x;
    if (i < NDV * H / 4) ((float4*)g_agg)[i] = make_float4(0.f, 0.f, 0.f, 0.f);
}
__global__ void k_deg(const int* __restrict__ dst) {
    int e = blockIdx.x * blockDim.x + threadIdx.x;
    if (e < NE) atomicAdd(&g_deg[dst[e]], 1.f);
}
__global__ void k_inv() {
    int i = blockIdx.x * blockDim.x + threadIdx.x;
    if (i < NDV) g_inv[i] = 1.f / fmaxf(g_deg[i], 1.f);
}

// ---- aggregation: warp-per-8-edges, batched gathers for MLP=8 -----------------
#define EB 8                                   // NE % EB == 0
__global__ void k_agg(const int* __restrict__ src, const int* __restrict__ dst,
                      const float* __restrict__ hext, int use_gh) {
    int warp = (blockIdx.x * blockDim.x + threadIdx.x) >> 5;
    int lane = threadIdx.x & 31;
    int e0 = warp * EB;
    if (e0 >= NE) return;
    const float* h = use_gh ? (const float*)g_h : hext;

    int s[EB], d[EB];
    #pragma unroll
    for (int j = 0; j < EB; ++j) { s[j] = src[e0 + j]; d[j] = dst[e0 + j]; }

    float4 v[EB];
    #pragma unroll
    for (int j = 0; j < EB; ++j)
        v[j] = ((const float4*)(h + (size_t)s[j] * H))[lane];

    #pragma unroll
    for (int j = 0; j < EB; ++j) {
        float* o = g_agg + (size_t)d[j] * H + lane * 4;
        red4(o, v[j].x, v[j].y, v[j].z, v[j].w);
    }
}

// ================= layers 0/1 GEMM via mma.sync bf16 (3-term split) ============
#define T64 ((NDV + 63) >> 6)
#define MM_BHI 0
#define MM_BLO 65536
#define MM_AHI 131072
#define MM_ALO 163840
#define MM_STAT 196608
#define MM_TOT (196608 + 1024)

__global__ __launch_bounds__(256, 1)
void k_gemm01mma(const float* __restrict__ Aext, int use_gh,
                 const float* __restrict__ Wself, const float* __restrict__ Wneigh) {
    extern __shared__ char smem[];
    uint32_t sb = s2u(smem);
    float* ssum = (float*)(smem + MM_STAT);
    float* ssq  = ssum + H;
    const int tid = threadIdx.x, lane = tid & 31, wid = tid >> 5;
    const float* A = use_gh ? (const float*)g_h : Aext;

    for (int it = 0; it < 16; ++it) {
        int idx = tid + (it << 8);
        int k = idx >> 4, nc = idx & 15, n0 = nc << 3;
        const float* wsrc = (k < 128) ? (Wself + k * H + n0) : (Wneigh + (k - 128) * H + n0);
        float4 v0 = *(const float4*)(wsrc);
        float4 v1 = *(const float4*)(wsrc + 4);
        uint32_t off = (uint32_t)k * 256 + (uint32_t)((nc ^ (k & 7)) << 4);
        *(uint4*)(smem + MM_BHI + off) = make_uint4(
            pkbf(v0.x, v0.y), pkbf(v0.z, v0.w), pkbf(v1.x, v1.y), pkbf(v1.z, v1.w));
        *(uint4*)(smem + MM_BLO + off) = make_uint4(
            pkbf(bflo(v0.x), bflo(v0.y)), pkbf(bflo(v0.z), bflo(v0.w)),
            pkbf(bflo(v1.x), bflo(v1.y)), pkbf(bflo(v1.z), bflo(v1.w)));
    }
    if (tid < H) { ssum[tid] = 0.f; ssq[tid] = 0.f; }
    __syncthreads();

    const int wm = wid & 1, wn = wid >> 1;
    const int rbase = wm << 5, nbase = wn << 5;
    const int l7 = lane & 7, kp = lane >> 4, l15 = lane & 15;
    const int g = lane >> 2, tq = lane & 3;
    const uint32_t aRowHi = sb + MM_AHI + (uint32_t)(rbase + l15) * 512;
    const uint32_t aRowLo = aRowHi + (MM_ALO - MM_AHI);
    const int nb0 = (nbase >> 3) + kp;
    const uint32_t bch0 = (uint32_t)((nb0 ^ l7) << 4);
    const uint32_t bch1 = (uint32_t)(((nb0 + 2) ^ l7) << 4);
    const uint32_t bHiBase = sb + MM_BHI + (uint32_t)l15 * 256;
    const uint32_t bLoBase = sb + MM_BLO + (uint32_t)l15 * 256;

    const int srow = tid >> 2, skq = (tid & 3) << 6;
    const bool selfHalf = skq < 128;
    float csum[8], csq[8];
    #pragma unroll
    for (int i = 0; i < 8; ++i) { csum[i] = 0.f; csq[i] = 0.f; }

    for (int t = blockIdx.x; t < T64; t += gridDim.x) {
        int t0 = t << 6;
        __syncthreads();
        {
            int rowg = t0 + srow;
            bool valid = rowg < NDV;
            float iv = (valid && !selfHalf) ? g_inv[rowg] : 1.f;
            const float* srcp = selfHalf ? (A + (size_t)rowg * H + skq)
                                         : (g_agg + (size_t)rowg * H + (skq - 128));
            uint32_t rowoff = (uint32_t)srow * 512;
            int rs = srow & 7;
            #pragma unroll
            for (int j = 0; j < 16; ++j) {
                float4 v = valid ? *(const float4*)(srcp + (j << 2))
                                 : make_float4(0.f, 0.f, 0.f, 0.f);
                if (!selfHalf) { v.x *= iv; v.y *= iv; v.z *= iv; v.w *= iv; }
                int k = skq + (j << 2);
                uint32_t off = rowoff + (uint32_t)(((k >> 3) ^ rs) << 4) + (uint32_t)((k & 7) << 1);
                *(uint2*)(smem + MM_AHI + off) = make_uint2(pkbf(v.x, v.y), pkbf(v.z, v.w));
                *(uint2*)(smem + MM_ALO + off) = make_uint2(pkbf(bflo(v.x), bflo(v.y)),
                                                            pkbf(bflo(v.z), bflo(v.w)));
            }
        }
        __syncthreads();

        float d[2][4][4];
        #pragma unroll
        for (int m = 0; m < 2; ++m)
            #pragma unroll
            for (int nb = 0; nb < 4; ++nb)
                #pragma unroll
                for (int e = 0; e < 4; ++e) d[m][nb][e] = 0.f;

        #pragma unroll 4
        for (int ks = 0; ks < 16; ++ks) {
            uint32_t ach = (uint32_t)((((ks << 1) + kp) ^ l7) << 4);
            uint32_t ahi0[4], ahi1[4], alo0[4], alo1[4];
            ldmA(ahi0, aRowHi + ach);
            ldmA(ahi1, aRowHi + 8192 + ach);
            ldmA(alo0, aRowLo + ach);
            ldmA(alo1, aRowLo + 8192 + ach);
            uint32_t bks = (uint32_t)ks << 12;
            uint32_t bh0[4], bh1[4], bl0[4], bl1[4];
            ldmBT(bh0, bHiBase + bks + bch0);
            ldmBT(bh1, bHiBase + bks + bch1);
            ldmBT(bl0, bLoBase + bks + bch0);
            ldmBT(bl1, bLoBase + bks + bch1);
            mmabf(d[0][0], ahi0, bh0); mmabf(d[0][1], ahi0, bh0 + 2);
            mmabf(d[0][2], ahi0, bh1); mmabf(d[0][3], ahi0, bh1 + 2);
            mmabf(d[1][0], ahi1, bh0); mmabf(d[1][1], ahi1, bh0 + 2);
            mmabf(d[1][2], ahi1, bh1); mmabf(d[1][3], ahi1, bh1 + 2);
            mmabf(d[0][0], ahi0, bl0); mmabf(d[0][1], ahi0, bl0 + 2);
            mmabf(d[0][2], ahi0, bl1); mmabf(d[0][3], ahi0, bl1 + 2);
            mmabf(d[1][0], ahi1, bl0); mmabf(d[1][1], ahi1, bl0 + 2);
            mmabf(d[1][2], ahi1, bl1); mmabf(d[1][3], ahi1, bl1 + 2);
            mmabf(d[0][0], alo0, bh0); mmabf(d[0][1], alo0, bh0 + 2);
            mmabf(d[0][2], alo0, bh1); mmabf(d[0][3], alo0, bh1 + 2);
            mmabf(d[1][0], alo1, bh0); mmabf(d[1][1], alo1, bh0 + 2);
            mmabf(d[1][2], alo1, bh1); mmabf(d[1][3], alo1, bh1 + 2);
        }

        #pragma unroll
        for (int m = 0; m < 2; ++m) {
            int row0 = t0 + rbase + (m << 4) + g;
            int row1 = row0 + 8;
            if (row0 < NDV) {
                float* o = g_out + (size_t)row0 * H + nbase + (tq << 1);
                #pragma unroll
                for (int nb = 0; nb < 4; ++nb) {
                    *(float2*)(o + (nb << 3)) = make_float2(d[m][nb][0], d[m][nb][1]);
                    csum[nb * 2 + 0] += d[m][nb][0]; csq[nb * 2 + 0] += d[m][nb][0] * d[m][nb][0];
                    csum[nb * 2 + 1] += d[m][nb][1]; csq[nb * 2 + 1] += d[m][nb][1] * d[m][nb][1];
                }
            }
            if (row1 < NDV) {
                float* o = g_out + (size_t)row1 * H + nbase + (tq << 1);
                #pragma unroll
                for (int nb = 0; nb < 4; ++nb) {
                    *(float2*)(o + (nb << 3)) = make_float2(d[m][nb][2], d[m][nb][3]);
                    csum[nb * 2 + 0] += d[m][nb][2]; csq[nb * 2 + 0] += d[m][nb][2] * d[m][nb][2];
                    csum[nb * 2 + 1] += d[m][nb][3]; csq[nb * 2 + 1] += d[m][nb][3] * d[m][nb][3];
                }
            }
        }
    }

    #pragma unroll
    for (int nb = 0; nb < 4; ++nb)
        #pragma unroll
        for (int j = 0; j < 2; ++j) {
            int col = nbase + (tq << 1) + (nb << 3) + j;
            atomicAdd(&ssum[col], csum[nb * 2 + j]);
            atomicAdd(&ssq[col],  csq[nb * 2 + j]);
        }
    __syncthreads();
    if (tid < H) {
        atomicAdd(&g_sum[tid], ssum[tid]);
        atomicAdd(&g_sq[tid],  ssq[tid]);
    }
}

// consumes stats AND re-zeroes them (replay-invariant)
__global__ void k_bnfin(const float* __restrict__ gamma, const float* __restrict__ beta) {
    int c = threadIdx.x;
    float mean = g_sum[c] * (1.f / NDV);
    float var  = g_sq[c]  * (1.f / NDV) - mean * mean;
    float sc = gamma[c] * rsqrtf(var + 1e-5f);
    g_scale[c] = sc;
    g_shift[c] = beta[c] - mean * sc;
    g_sum[c] = 0.f;
    g_sq[c]  = 0.f;
}

// once-per-node BN+ReLU: g_h = relu(g_out*scale+shift)
__global__ void k_apply() {
    int i = blockIdx.x * blockDim.x + threadIdx.x;
    if (i >= NDV * 32) return;
    int c4 = i & 31;
    float4 v  = ((const float4*)g_out)[i];
    float4 sc = ((const float4*)g_scale)[c4];
    float4 sh = ((const float4*)g_shift)[c4];
    v.x = fmaxf(fmaf(v.x, sc.x, sh.x), 0.f);
    v.y = fmaxf(fmaf(v.y, sc.y, sh.y), 0.f);
    v.z = fmaxf(fmaf(v.z, sc.z, sh.z), 0.f);
    v.w = fmaxf(fmaf(v.w, sc.w, sh.w), 0.f);
    ((float4*)g_h)[i] = v;
}

// ================= layer 2 GEMM via mma.sync bf16 (3-term split) ===============
#define M2_BHI 0
#define M2_BLO 32768
#define M2_AHI 65536
#define M2_ALO 81920
#define M2_TOT 98304

__global__ __launch_bounds__(256, 1)
void k_gemm2mma(const float* __restrict__ Wself, const float* __restrict__ Wneigh,
                const float* __restrict__ bias, float* __restrict__ out) {
    extern __shared__ char smem[];
    uint32_t sb = s2u(smem);
    const int tid = threadIdx.x, lane = tid & 31, wid = tid >> 5;

    for (int it = 0; it < 8; ++it) {
        int idx = tid + (it << 8);
        int k = idx >> 4, nc = idx & 15, n0 = nc << 3;
        float4 v0 = make_float4(0.f, 0.f, 0.f, 0.f), v1 = v0;
        if (n0 < 40) {
            const float* w = Wself + k * OD + n0;
            v0 = *(const float4*)(w); v1 = *(const float4*)(w + 4);
        } else if (n0 < 80) {
            const float* w = Wneigh + k * OD + (n0 - 40);
            v0 = *(const float4*)(w); v1 = *(const float4*)(w + 4);
        }
        uint32_t off = (uint32_t)k * 256 + (uint32_t)((nc ^ (k & 7)) << 4);
        *(uint4*)(smem + M2_BHI + off) = make_uint4(
            pkbf(v0.x, v0.y), pkbf(v0.z, v0.w), pkbf(v1.x, v1.y), pkbf(v1.z, v1.w));
        *(uint4*)(smem + M2_BLO + off) = make_uint4(
            pkbf(bflo(v0.x), bflo(v0.y)), pkbf(bflo(v0.z), bflo(v0.w)),
            pkbf(bflo(v1.x), bflo(v1.y)), pkbf(bflo(v1.z), bflo(v1.w)));
    }
    __syncthreads();

    const int wm = wid & 1, wn = wid >> 1;
    const int rbase = wm << 5, nbase = wn << 5;
    const int l7 = lane & 7, kp = lane >> 4, l15 = lane & 15;
    const int g = lane >> 2, tq = lane & 3;
    const uint32_t aRowHi = sb + M2_AHI + (uint32_t)(rbase + l15) * 256;
    const uint32_t aRowLo = aRowHi + (M2_ALO - M2_AHI);
    const int nb0 = (nbase >> 3) + kp;
    const uint32_t bch0 = (uint32_t)((nb0 ^ l7) << 4);
    const uint32_t bch1 = (uint32_t)(((nb0 + 2) ^ l7) << 4);
    const uint32_t bHiBase = sb + M2_BHI + (uint32_t)l15 * 256;
    const uint32_t bLoBase = sb + M2_BLO + (uint32_t)l15 * 256;

    const int srow = tid >> 2, skq = (tid & 3) << 5;

    for (int t = blockIdx.x; t < T64; t += gridDim.x) {
        int t0 = t << 6;
        __syncthreads();
        {
            int rowg = t0 + srow;
            bool valid = rowg < NDV;
            const float* srcp = (const float*)g_h + (size_t)rowg * H + skq;
            uint32_t rowoff = (uint32_t)srow * 256;
            int rs = srow & 7;
            #pragma unroll
            for (int j = 0; j < 8; ++j) {
                float4 v = valid ? *(const float4*)(srcp + (j << 2))
                                 : make_float4(0.f, 0.f, 0.f, 0.f);
                int k = skq + (j << 2);
                uint32_t off = rowoff + (uint32_t)(((k >> 3) ^ rs) << 4) + (uint32_t)((k & 7) << 1);
                *(uint2*)(smem + M2_AHI + off) = make_uint2(pkbf(v.x, v.y), pkbf(v.z, v.w));
                *(uint2*)(smem + M2_ALO + off) = make_uint2(pkbf(bflo(v.x), bflo(v.y)),
                                                            pkbf(bflo(v.z), bflo(v.w)));
            }
        }
        __syncthreads();

        float d[2][4][4];
        #pragma unroll
        for (int m = 0; m < 2; ++m)
            #pragma unroll
            for (int nb = 0; nb < 4; ++nb)
                #pragma unroll
                for (int e = 0; e < 4; ++e) d[m][nb][e] = 0.f;

        #pragma unroll 4
        for (int ks = 0; ks < 8; ++ks) {
            uint32_t ach = (uint32_t)((((ks << 1) + kp) ^ l7) << 4);
            uint32_t ahi0[4], ahi1[4], alo0[4], alo1[4];
            ldmA(ahi0, aRowHi + ach);
            ldmA(ahi1, aRowHi + 4096 + ach);
            ldmA(alo0, aRowLo + ach);
            ldmA(alo1, aRowLo + 4096 + ach);
            uint32_t bks = (uint32_t)ks << 12;
            uint32_t bh0[4], bh1[4], bl0[4], bl1[4];
            ldmBT(bh0, bHiBase + bks + bch0);
            ldmBT(bh1, bHiBase + bks + bch1);
            ldmBT(bl0, bLoBase + bks + bch0);
            ldmBT(bl1, bLoBase + bks + bch1);
            mmabf(d[0][0], ahi0, bh0); mmabf(d[0][1], ahi0, bh0 + 2);
            mmabf(d[0][2], ahi0, bh1); mmabf(d[0][3], ahi0, bh1 + 2);
            mmabf(d[1][0], ahi1, bh0); mmabf(d[1][1], ahi1, bh0 + 2);
            mmabf(d[1][2], ahi1, bh1); mmabf(d[1][3], ahi1, bh1 + 2);
            mmabf(d[0][0], ahi0, bl0); mmabf(d[0][1], ahi0, bl0 + 2);
            mmabf(d[0][2], ahi0, bl1); mmabf(d[0][3], ahi0, bl1 + 2);
            mmabf(d[1][0], ahi1, bl0); mmabf(d[1][1], ahi1, bl0 + 2);
            mmabf(d[1][2], ahi1, bl1); mmabf(d[1][3], ahi1, bl1 + 2);
            mmabf(d[0][0], alo0, bh0); mmabf(d[0][1], alo0, bh0 + 2);
            mmabf(d[0][2], alo0, bh1); mmabf(d[0][3], alo0, bh1 + 2);
            mmabf(d[1][0], alo1, bh0); mmabf(d[1][1], alo1, bh0 + 2);
            mmabf(d[1][2], alo1, bh1); mmabf(d[1][3], alo1, bh1 + 2);
        }

        #pragma unroll
        for (int m = 0; m < 2; ++m) {
            int row0 = t0 + rbase + (m << 4) + g;
            int row1 = row0 + 8;
            #pragma unroll
            for (int nb = 0; nb < 4; ++nb) {
                int col = nbase + (tq << 1) + (nb << 3);
                #pragma unroll
                for (int j = 0; j < 2; ++j) {
                    int c = col + j;
                    if (c < 40) {
                        if (row0 < NDV) out[(size_t)row0 * OD + c] = d[m][nb][j] + bias[c];
                        if (row1 < NDV) out[(size_t)row1 * OD + c] = d[m][nb][j + 2] + bias[c];
                    } else if (c < 80) {
                        if (row0 < NDV) g_p[(size_t)row0 * OD + c - 40] = d[m][nb][j];
                        if (row1 < NDV) g_p[(size_t)row1 * OD + c - 40] = d[m][nb][j + 2];
                    }
                }
            }
        }
    }
}

// out[dst] += p[src] * inv_deg[dst] ; thread handles 4 edges for its 16B chunk
__global__ void k_edge2(const int* __restrict__ src, const int* __restrict__ dst,
                        float* __restrict__ out) {
    int idx = blockIdx.x * blockDim.x + threadIdx.x;   // over (NE/4)*10
    if (idx >= (NE / 4) * 10) return;
    int eq = idx / 10, c4 = idx - eq * 10;
    int e0 = eq * 4;
    int s[4], d[4];
    #pragma unroll
    for (int j = 0; j < 4; ++j) { s[j] = src[e0 + j]; d[j] = dst[e0 + j]; }
    float4 v[4];
    #pragma unroll
    for (int j = 0; j < 4; ++j)
        v[j] = *(const float4*)(g_p + (size_t)s[j] * OD + c4 * 4);
    float iv[4];
    #pragma unroll
    for (int j = 0; j < 4; ++j) iv[j] = g_inv[d[j]];
    #pragma unroll
    for (int j = 0; j < 4; ++j) {
        float* o = out + (size_t)d[j] * OD + c4 * 4;
        red4(o, v[j].x * iv[j], v[j].y * iv[j], v[j].z * iv[j], v[j].w * iv[j]);
    }
}

// ---------------- host launcher ------------------------------------------------
extern "C" void kernel_launch(void* const* d_in, const int* in_sizes, int n_in,
                              void* d_out, int out_size) {
    const float* feat = (const float*)d_in[0];
    const int*   src  = (const int*)d_in[1];
    const int*   dst  = (const int*)d_in[2];
    const float* Ws0 = (const float*)d_in[3];
    const float* Wn0 = (const float*)d_in[4];
    const float* ga0 = (const float*)d_in[5];
    const float* be0 = (const float*)d_in[6];
    const float* Ws1 = (const float*)d_in[7];
    const float* Wn1 = (const float*)d_in[8];
    const float* ga1 = (const float*)d_in[9];
    const float* be1 = (const float*)d_in[10];
    const float* Ws2 = (const float*)d_in[11];
    const float* Wn2 = (const float*)d_in[12];
    const float* b2  = (const float*)d_in[13];
    float* out = (float*)d_out;

    cudaFuncSetAttribute(k_gemm01mma, cudaFuncAttributeMaxDynamicSharedMemorySize, MM_TOT);
    cudaFuncSetAttribute(k_gemm2mma,  cudaFuncAttributeMaxDynamicSharedMemorySize, M2_TOT);

    const int TB = 256;
    const int AGG_BLOCKS = (NE / EB * 32 + TB - 1) / TB;   // 100k warps
    // slot 4 = k_agg (profiled)
    k_zero_deg<<<(NDV + TB - 1) / TB, TB>>>();                                  // 1
    k_zero_agg<<<(NDV * H / 4 + TB - 1) / TB, TB>>>();                          // 2
    k_deg<<<(NE + TB - 1) / TB, TB>>>(dst);                                     // 3
    k_agg<<<AGG_BLOCKS, TB>>>(src, dst, feat, 0);                               // 4 <- profiled
    k_inv<<<(NDV + TB - 1) / TB, TB>>>();                                       // 5
    k_gemm01mma<<<148, 256, MM_TOT>>>(feat, 0, Ws0, Wn0);
    k_bnfin<<<1, 128>>>(ga0, be0);
    k_apply<<<(NDV * 32 + TB - 1) / TB, TB>>>();

    // ---- layer 1 ----
    k_zero_agg<<<(NDV * H / 4 + TB - 1) / TB, TB>>>();
    k_agg<<<AGG_BLOCKS, TB>>>(src, dst, nullptr, 1);
    k_gemm01mma<<<148, 256, MM_TOT>>>(nullptr, 1, Ws1, Wn1);
    k_bnfin<<<1, 128>>>(ga1, be1);
    k_apply<<<(NDV * 32 + TB - 1) / TB, TB>>>();

    // ---- layer 2 ----
    k_gemm2mma<<<148, 256, M2_TOT>>>(Ws2, Wn2, b2, out);
    k_edge2<<<((NE / 4) * 10 + TB - 1) / TB, TB>>>(src, dst, out);

    (void)in_sizes; (void)n_in; (void)out_size;
}

// round 11
// speedup vs baseline: 1.3856x; 1.0279x over previous
#include <cuda_runtime.h>
#include <cuda_bf16.h>
#include <cstdint>

#define NDV 100000
#define NE  800000
#define H   128
#define OD  40

// ---------------- device scratch (static globals: allocation-free) -------------
__device__ float g_agg[(size_t)NDV * H];
__device__ float g_out[(size_t)NDV * H];
__device__ float g_h  [(size_t)NDV * H];
__device__ float g_p  [(size_t)NDV * OD];
__device__ float g_deg[NDV];
__device__ float g_sum[H];      // zero at load; k_bnfin re-zeroes after consuming
__device__ float g_sq [H];
__device__ float g_scale[H];
__device__ float g_shift[H];

// ---------------- helpers ------------------------------------------------------
__device__ __forceinline__ uint32_t s2u(const void* p) {
    uint32_t a;
    asm("{ .reg .u64 t; cvta.to.shared.u64 t, %1; cvt.u32.u64 %0, t; }" : "=r"(a) : "l"(p));
    return a;
}
__device__ __forceinline__ void red4(float* p, float x, float y, float z, float w) {
    asm volatile("red.global.add.v4.f32 [%0], {%1,%2,%3,%4};"
                 :: "l"(p), "f"(x), "f"(y), "f"(z), "f"(w) : "memory");
}
__device__ __forceinline__ uint32_t pkbf(float a, float b) {
    __nv_bfloat162 t = __halves2bfloat162(__float2bfloat16(a), __float2bfloat16(b));
    return *(uint32_t*)&t;
}
__device__ __forceinline__ float bflo(float x) {
    __nv_bfloat16 h = __float2bfloat16(x);
    return x - __bfloat162float(h);
}
__device__ __forceinline__ void ldmA(uint32_t* r, uint32_t a) {
    asm volatile("ldmatrix.sync.aligned.m8n8.x4.shared.b16 {%0,%1,%2,%3},[%4];"
                 : "=r"(r[0]), "=r"(r[1]), "=r"(r[2]), "=r"(r[3]) : "r"(a));
}
__device__ __forceinline__ void ldmBT(uint32_t* r, uint32_t a) {
    asm volatile("ldmatrix.sync.aligned.m8n8.x4.trans.shared.b16 {%0,%1,%2,%3},[%4];"
                 : "=r"(r[0]), "=r"(r[1]), "=r"(r[2]), "=r"(r[3]) : "r"(a));
}
__device__ __forceinline__ void mmabf(float* d, const uint32_t* a, const uint32_t* b) {
    asm volatile("mma.sync.aligned.m16n8k16.row.col.f32.bf16.bf16.f32 "
                 "{%0,%1,%2,%3},{%4,%5,%6,%7},{%8,%9},{%0,%1,%2,%3};"
                 : "+f"(d[0]), "+f"(d[1]), "+f"(d[2]), "+f"(d[3])
                 : "r"(a[0]), "r"(a[1]), "r"(a[2]), "r"(a[3]), "r"(b[0]), "r"(b[1]));
}

// ---------------- small kernels ------------------------------------------------
__global__ void k_zero0() {          // fused: deg=0, agg=0
    int i = blockIdx.x * blockDim.x + threadIdx.x;
    if (i < NDV) g_deg[i] = 0.f;
    if (i < NDV * H / 4) ((float4*)g_agg)[i] = make_float4(0.f, 0.f, 0.f, 0.f);
}
__global__ void k_zero_agg() {
    int i = blockIdx.x * blockDim.x + threadIdx.x;
    if (i < NDV * H / 4) ((float4*)g_agg)[i] = make_float4(0.f, 0.f, 0.f, 0.f);
}
__global__ void k_deg(const int* __restrict__ dst) {
    int e = blockIdx.x * blockDim.x + threadIdx.x;
    if (e < NE) atomicAdd(&g_deg[dst[e]], 1.f);
}

// ---- aggregation: warp-per-8-edges, batched gathers for MLP=8 -----------------
#define EB 8
__global__ void k_agg(const int* __restrict__ src, const int* __restrict__ dst,
                      const float* __restrict__ hext, int use_gh) {
    int warp = (blockIdx.x * blockDim.x + threadIdx.x) >> 5;
    int lane = threadIdx.x & 31;
    int e0 = warp * EB;
    if (e0 >= NE) return;
    const float* h = use_gh ? (const float*)g_h : hext;

    int s[EB], d[EB];
    #pragma unroll
    for (int j = 0; j < EB; ++j) { s[j] = src[e0 + j]; d[j] = dst[e0 + j]; }

    float4 v[EB];
    #pragma unroll
    for (int j = 0; j < EB; ++j)
        v[j] = ((const float4*)(h + (size_t)s[j] * H))[lane];

    #pragma unroll
    for (int j = 0; j < EB; ++j) {
        float* o = g_agg + (size_t)d[j] * H + lane * 4;
        red4(o, v[j].x, v[j].y, v[j].z, v[j].w);
    }
}

// ================= layers 0/1 GEMM via mma.sync bf16 (3-term split) ============
// register-prefetch pipelined staging: tile t+1's LDGs issue before tile t's MMAs
#define T64 ((NDV + 63) >> 6)
#define MM_BHI 0
#define MM_BLO 65536
#define MM_AHI 131072
#define MM_ALO 163840
#define MM_STAT 196608
#define MM_TOT (196608 + 1024)

__global__ __launch_bounds__(256, 1)
void k_gemm01mma(const float* __restrict__ Aext, int use_gh,
                 const float* __restrict__ Wself, const float* __restrict__ Wneigh) {
    extern __shared__ char smem[];
    uint32_t sb = s2u(smem);
    float* ssum = (float*)(smem + MM_STAT);
    float* ssq  = ssum + H;
    const int tid = threadIdx.x, lane = tid & 31, wid = tid >> 5;
    const float* A = use_gh ? (const float*)g_h : Aext;

    for (int it = 0; it < 16; ++it) {
        int idx = tid + (it << 8);
        int k = idx >> 4, nc = idx & 15, n0 = nc << 3;
        const float* wsrc = (k < 128) ? (Wself + k * H + n0) : (Wneigh + (k - 128) * H + n0);
        float4 v0 = *(const float4*)(wsrc);
        float4 v1 = *(const float4*)(wsrc + 4);
        uint32_t off = (uint32_t)k * 256 + (uint32_t)((nc ^ (k & 7)) << 4);
        *(uint4*)(smem + MM_BHI + off) = make_uint4(
            pkbf(v0.x, v0.y), pkbf(v0.z, v0.w), pkbf(v1.x, v1.y), pkbf(v1.z, v1.w));
        *(uint4*)(smem + MM_BLO + off) = make_uint4(
            pkbf(bflo(v0.x), bflo(v0.y)), pkbf(bflo(v0.z), bflo(v0.w)),
            pkbf(bflo(v1.x), bflo(v1.y)), pkbf(bflo(v1.z), bflo(v1.w)));
    }
    if (tid < H) { ssum[tid] = 0.f; ssq[tid] = 0.f; }
    __syncthreads();

    const int wm = wid & 1, wn = wid >> 1;
    const int rbase = wm << 5, nbase = wn << 5;
    const int l7 = lane & 7, kp = lane >> 4, l15 = lane & 15;
    const int g = lane >> 2, tq = lane & 3;
    const uint32_t aRowHi = sb + MM_AHI + (uint32_t)(rbase + l15) * 512;
    const uint32_t aRowLo = aRowHi + (MM_ALO - MM_AHI);
    const int nb0 = (nbase >> 3) + kp;
    const uint32_t bch0 = (uint32_t)((nb0 ^ l7) << 4);
    const uint32_t bch1 = (uint32_t)(((nb0 + 2) ^ l7) << 4);
    const uint32_t bHiBase = sb + MM_BHI + (uint32_t)l15 * 256;
    const uint32_t bLoBase = sb + MM_BLO + (uint32_t)l15 * 256;

    const int srow = tid >> 2, skq = (tid & 3) << 6;
    const bool selfHalf = skq < 128;
    float csum[8], csq[8];
    #pragma unroll
    for (int i = 0; i < 8; ++i) { csum[i] = 0.f; csq[i] = 0.f; }

    float4 pre[16];
    float predeg = 1.f;
    auto do_prefetch = [&](int t0p) {
        int rowg = t0p + srow;
        bool valid = rowg < NDV;
        predeg = (valid && !selfHalf) ? g_deg[rowg] : 1.f;
        const float* srcp = selfHalf ? (A + (size_t)rowg * H + skq)
                                     : (g_agg + (size_t)rowg * H + (skq - 128));
        #pragma unroll
        for (int j = 0; j < 16; ++j)
            pre[j] = valid ? *(const float4*)(srcp + (j << 2))
                           : make_float4(0.f, 0.f, 0.f, 0.f);
    };

    do_prefetch(blockIdx.x << 6);

    for (int t = blockIdx.x; t < T64; t += gridDim.x) {
        int t0 = t << 6;
        __syncthreads();
        // ---- convert prefetched registers -> smem (ALU only) ----
        {
            float iv = selfHalf ? 1.f : (1.f / fmaxf(predeg, 1.f));
            uint32_t rowoff = (uint32_t)srow * 512;
            int rs = srow & 7;
            #pragma unroll
            for (int j = 0; j < 16; ++j) {
                float4 v = pre[j];
                if (!selfHalf) { v.x *= iv; v.y *= iv; v.z *= iv; v.w *= iv; }
                int k = skq + (j << 2);
                uint32_t off = rowoff + (uint32_t)(((k >> 3) ^ rs) << 4) + (uint32_t)((k & 7) << 1);
                *(uint2*)(smem + MM_AHI + off) = make_uint2(pkbf(v.x, v.y), pkbf(v.z, v.w));
                *(uint2*)(smem + MM_ALO + off) = make_uint2(pkbf(bflo(v.x), bflo(v.y)),
                                                            pkbf(bflo(v.z), bflo(v.w)));
            }
        }
        __syncthreads();
        // ---- issue next tile's LDGs (latency hides behind MMAs below) ----
        int tn = t + gridDim.x;
        if (tn < T64) do_prefetch(tn << 6);

        float d[2][4][4];
        #pragma unroll
        for (int m = 0; m < 2; ++m)
            #pragma unroll
            for (int nb = 0; nb < 4; ++nb)
                #pragma unroll
                for (int e = 0; e < 4; ++e) d[m][nb][e] = 0.f;

        #pragma unroll 4
        for (int ks = 0; ks < 16; ++ks) {
            uint32_t ach = (uint32_t)((((ks << 1) + kp) ^ l7) << 4);
            uint32_t ahi0[4], ahi1[4], alo0[4], alo1[4];
            ldmA(ahi0, aRowHi + ach);
            ldmA(ahi1, aRowHi + 8192 + ach);
            ldmA(alo0, aRowLo + ach);
            ldmA(alo1, aRowLo + 8192 + ach);
            uint32_t bks = (uint32_t)ks << 12;
            uint32_t bh0[4], bh1[4], bl0[4], bl1[4];
            ldmBT(bh0, bHiBase + bks + bch0);
            ldmBT(bh1, bHiBase + bks + bch1);
            ldmBT(bl0, bLoBase + bks + bch0);
            ldmBT(bl1, bLoBase + bks + bch1);
            mmabf(d[0][0], ahi0, bh0); mmabf(d[0][1], ahi0, bh0 + 2);
            mmabf(d[0][2], ahi0, bh1); mmabf(d[0][3], ahi0, bh1 + 2);
            mmabf(d[1][0], ahi1, bh0); mmabf(d[1][1], ahi1, bh0 + 2);
            mmabf(d[1][2], ahi1, bh1); mmabf(d[1][3], ahi1, bh1 + 2);
            mmabf(d[0][0], ahi0, bl0); mmabf(d[0][1], ahi0, bl0 + 2);
            mmabf(d[0][2], ahi0, bl1); mmabf(d[0][3], ahi0, bl1 + 2);
            mmabf(d[1][0], ahi1, bl0); mmabf(d[1][1], ahi1, bl0 + 2);
            mmabf(d[1][2], ahi1, bl1); mmabf(d[1][3], ahi1, bl1 + 2);
            mmabf(d[0][0], alo0, bh0); mmabf(d[0][1], alo0, bh0 + 2);
            mmabf(d[0][2], alo0, bh1); mmabf(d[0][3], alo0, bh1 + 2);
            mmabf(d[1][0], alo1, bh0); mmabf(d[1][1], alo1, bh0 + 2);
            mmabf(d[1][2], alo1, bh1); mmabf(d[1][3], alo1, bh1 + 2);
        }

        #pragma unroll
        for (int m = 0; m < 2; ++m) {
            int row0 = t0 + rbase + (m << 4) + g;
            int row1 = row0 + 8;
            if (row0 < NDV) {
                float* o = g_out + (size_t)row0 * H + nbase + (tq << 1);
                #pragma unroll
                for (int nb = 0; nb < 4; ++nb) {
                    *(float2*)(o + (nb << 3)) = make_float2(d[m][nb][0], d[m][nb][1]);
                    csum[nb * 2 + 0] += d[m][nb][0]; csq[nb * 2 + 0] += d[m][nb][0] * d[m][nb][0];
                    csum[nb * 2 + 1] += d[m][nb][1]; csq[nb * 2 + 1] += d[m][nb][1] * d[m][nb][1];
                }
            }
            if (row1 < NDV) {
                float* o = g_out + (size_t)row1 * H + nbase + (tq << 1);
                #pragma unroll
                for (int nb = 0; nb < 4; ++nb) {
                    *(float2*)(o + (nb << 3)) = make_float2(d[m][nb][2], d[m][nb][3]);
                    csum[nb * 2 + 0] += d[m][nb][2]; csq[nb * 2 + 0] += d[m][nb][2] * d[m][nb][2];
                    csum[nb * 2 + 1] += d[m][nb][3]; csq[nb * 2 + 1] += d[m][nb][3] * d[m][nb][3];
                }
            }
        }
    }

    #pragma unroll
    for (int nb = 0; nb < 4; ++nb)
        #pragma unroll
        for (int j = 0; j < 2; ++j) {
            int col = nbase + (tq << 1) + (nb << 3) + j;
            atomicAdd(&ssum[col], csum[nb * 2 + j]);
            atomicAdd(&ssq[col],  csq[nb * 2 + j]);
        }
    __syncthreads();
    if (tid < H) {
        atomicAdd(&g_sum[tid], ssum[tid]);
        atomicAdd(&g_sq[tid],  ssq[tid]);
    }
}

// consumes stats AND re-zeroes them (replay-invariant)
__global__ void k_bnfin(const float* __restrict__ gamma, const float* __restrict__ beta) {
    int c = threadIdx.x;
    float mean = g_sum[c] * (1.f / NDV);
    float var  = g_sq[c]  * (1.f / NDV) - mean * mean;
    float sc = gamma[c] * rsqrtf(var + 1e-5f);
    g_scale[c] = sc;
    g_shift[c] = beta[c] - mean * sc;
    g_sum[c] = 0.f;
    g_sq[c]  = 0.f;
}

// once-per-node BN+ReLU: g_h = relu(g_out*scale+shift)
__global__ void k_apply() {
    int i = blockIdx.x * blockDim.x + threadIdx.x;
    if (i >= NDV * 32) return;
    int c4 = i & 31;
    float4 v  = ((const float4*)g_out)[i];
    float4 sc = ((const float4*)g_scale)[c4];
    float4 sh = ((const float4*)g_shift)[c4];
    v.x = fmaxf(fmaf(v.x, sc.x, sh.x), 0.f);
    v.y = fmaxf(fmaf(v.y, sc.y, sh.y), 0.f);
    v.z = fmaxf(fmaf(v.z, sc.z, sh.z), 0.f);
    v.w = fmaxf(fmaf(v.w, sc.w, sh.w), 0.f);
    ((float4*)g_h)[i] = v;
}

// ================= layer 2 GEMM via mma.sync bf16 (3-term split) ===============
#define M2_BHI 0
#define M2_BLO 32768
#define M2_AHI 65536
#define M2_ALO 81920
#define M2_TOT 98304

__global__ __launch_bounds__(256, 1)
void k_gemm2mma(const float* __restrict__ Wself, const float* __restrict__ Wneigh,
                const float* __restrict__ bias, float* __restrict__ out) {
    extern __shared__ char smem[];
    uint32_t sb = s2u(smem);
    const int tid = threadIdx.x, lane = tid & 31, wid = tid >> 5;

    for (int it = 0; it < 8; ++it) {
        int idx = tid + (it << 8);
        int k = idx >> 4, nc = idx & 15, n0 = nc << 3;
        float4 v0 = make_float4(0.f, 0.f, 0.f, 0.f), v1 = v0;
        if (n0 < 40) {
            const float* w = Wself + k * OD + n0;
            v0 = *(const float4*)(w); v1 = *(const float4*)(w + 4);
        } else if (n0 < 80) {
            const float* w = Wneigh + k * OD + (n0 - 40);
            v0 = *(const float4*)(w); v1 = *(const float4*)(w + 4);
        }
        uint32_t off = (uint32_t)k * 256 + (uint32_t)((nc ^ (k & 7)) << 4);
        *(uint4*)(smem + M2_BHI + off) = make_uint4(
            pkbf(v0.x, v0.y), pkbf(v0.z, v0.w), pkbf(v1.x, v1.y), pkbf(v1.z, v1.w));
        *(uint4*)(smem + M2_BLO + off) = make_uint4(
            pkbf(bflo(v0.x), bflo(v0.y)), pkbf(bflo(v0.z), bflo(v0.w)),
            pkbf(bflo(v1.x), bflo(v1.y)), pkbf(bflo(v1.z), bflo(v1.w)));
    }
    __syncthreads();

    const int wm = wid & 1, wn = wid >> 1;
    const int rbase = wm << 5, nbase = wn << 5;
    const int l7 = lane & 7, kp = lane >> 4, l15 = lane & 15;
    const int g = lane >> 2, tq = lane & 3;
    const uint32_t aRowHi = sb + M2_AHI + (uint32_t)(rbase + l15) * 256;
    const uint32_t aRowLo = aRowHi + (M2_ALO - M2_AHI);
    const int nb0 = (nbase >> 3) + kp;
    const uint32_t bch0 = (uint32_t)((nb0 ^ l7) << 4);
    const uint32_t bch1 = (uint32_t)(((nb0 + 2) ^ l7) << 4);
    const uint32_t bHiBase = sb + M2_BHI + (uint32_t)l15 * 256;
    const uint32_t bLoBase = sb + M2_BLO + (uint32_t)l15 * 256;

    const int srow = tid >> 2, skq = (tid & 3) << 5;

    for (int t = blockIdx.x; t < T64; t += gridDim.x) {
        int t0 = t << 6;
        __syncthreads();
        {
            int rowg = t0 + srow;
            bool valid = rowg < NDV;
            const float* srcp = (const float*)g_h + (size_t)rowg * H + skq;
            uint32_t rowoff = (uint32_t)srow * 256;
            int rs = srow & 7;
            #pragma unroll
            for (int j = 0; j < 8; ++j) {
                float4 v = valid ? *(const float4*)(srcp + (j << 2))
                                 : make_float4(0.f, 0.f, 0.f, 0.f);
                int k = skq + (j << 2);
                uint32_t off = rowoff + (uint32_t)(((k >> 3) ^ rs) << 4) + (uint32_t)((k & 7) << 1);
                *(uint2*)(smem + M2_AHI + off) = make_uint2(pkbf(v.x, v.y), pkbf(v.z, v.w));
                *(uint2*)(smem + M2_ALO + off) = make_uint2(pkbf(bflo(v.x), bflo(v.y)),
                                                            pkbf(bflo(v.z), bflo(v.w)));
            }
        }
        __syncthreads();

        float d[2][4][4];
        #pragma unroll
        for (int m = 0; m < 2; ++m)
            #pragma unroll
            for (int nb = 0; nb < 4; ++nb)
                #pragma unroll
                for (int e = 0; e < 4; ++e) d[m][nb][e] = 0.f;

        #pragma unroll 4
        for (int ks = 0; ks < 8; ++ks) {
            uint32_t ach = (uint32_t)((((ks << 1) + kp) ^ l7) << 4);
            uint32_t ahi0[4], ahi1[4], alo0[4], alo1[4];
            ldmA(ahi0, aRowHi + ach);
            ldmA(ahi1, aRowHi + 4096 + ach);
            ldmA(alo0, aRowLo + ach);
            ldmA(alo1, aRowLo + 4096 + ach);
            uint32_t bks = (uint32_t)ks << 12;
            uint32_t bh0[4], bh1[4], bl0[4], bl1[4];
            ldmBT(bh0, bHiBase + bks + bch0);
            ldmBT(bh1, bHiBase + bks + bch1);
            ldmBT(bl0, bLoBase + bks + bch0);
            ldmBT(bl1, bLoBase + bks + bch1);
            mmabf(d[0][0], ahi0, bh0); mmabf(d[0][1], ahi0, bh0 + 2);
            mmabf(d[0][2], ahi0, bh1); mmabf(d[0][3], ahi0, bh1 + 2);
            mmabf(d[1][0], ahi1, bh0); mmabf(d[1][1], ahi1, bh0 + 2);
            mmabf(d[1][2], ahi1, bh1); mmabf(d[1][3], ahi1, bh1 + 2);
            mmabf(d[0][0], ahi0, bl0); mmabf(d[0][1], ahi0, bl0 + 2);
            mmabf(d[0][2], ahi0, bl1); mmabf(d[0][3], ahi0, bl1 + 2);
            mmabf(d[1][0], ahi1, bl0); mmabf(d[1][1], ahi1, bl0 + 2);
            mmabf(d[1][2], ahi1, bl1); mmabf(d[1][3], ahi1, bl1 + 2);
            mmabf(d[0][0], alo0, bh0); mmabf(d[0][1], alo0, bh0 + 2);
            mmabf(d[0][2], alo0, bh1); mmabf(d[0][3], alo0, bh1 + 2);
            mmabf(d[1][0], alo1, bh0); mmabf(d[1][1], alo1, bh0 + 2);
            mmabf(d[1][2], alo1, bh1); mmabf(d[1][3], alo1, bh1 + 2);
        }

        #pragma unroll
        for (int m = 0; m < 2; ++m) {
            int row0 = t0 + rbase + (m << 4) + g;
            int row1 = row0 + 8;
            #pragma unroll
            for (int nb = 0; nb < 4; ++nb) {
                int col = nbase + (tq << 1) + (nb << 3);
                #pragma unroll
                for (int j = 0; j < 2; ++j) {
                    int c = col + j;
                    if (c < 40) {
                        if (row0 < NDV) out[(size_t)row0 * OD + c] = d[m][nb][j] + bias[c];
                        if (row1 < NDV) out[(size_t)row1 * OD + c] = d[m][nb][j + 2] + bias[c];
                    } else if (c < 80) {
                        if (row0 < NDV) g_p[(size_t)row0 * OD + c - 40] = d[m][nb][j];
                        if (row1 < NDV) g_p[(size_t)row1 * OD + c - 40] = d[m][nb][j + 2];
                    }
                }
            }
        }
    }
}

// out[dst] += p[src] / max(deg[dst],1) ; thread handles 4 edges per 16B chunk
__global__ void k_edge2(const int* __restrict__ src, const int* __restrict__ dst,
                        float* __restrict__ out) {
    int idx = blockIdx.x * blockDim.x + threadIdx.x;
    if (idx >= (NE / 4) * 10) return;
    int eq = idx / 10, c4 = idx - eq * 10;
    int e0 = eq * 4;
    int s[4], d[4];
    #pragma unroll
    for (int j = 0; j < 4; ++j) { s[j] = src[e0 + j]; d[j] = dst[e0 + j]; }
    float4 v[4];
    #pragma unroll
    for (int j = 0; j < 4; ++j)
        v[j] = *(const float4*)(g_p + (size_t)s[j] * OD + c4 * 4);
    float iv[4];
    #pragma unroll
    for (int j = 0; j < 4; ++j) iv[j] = 1.f / fmaxf(g_deg[d[j]], 1.f);
    #pragma unroll
    for (int j = 0; j < 4; ++j) {
        float* o = out + (size_t)d[j] * OD + c4 * 4;
        red4(o, v[j].x * iv[j], v[j].y * iv[j], v[j].z * iv[j], v[j].w * iv[j]);
    }
}

// ---------------- host launcher ------------------------------------------------
extern "C" void kernel_launch(void* const* d_in, const int* in_sizes, int n_in,
                              void* d_out, int out_size) {
    const float* feat = (const float*)d_in[0];
    const int*   src  = (const int*)d_in[1];
    const int*   dst  = (const int*)d_in[2];
    const float* Ws0 = (const float*)d_in[3];
    const float* Wn0 = (const float*)d_in[4];
    const float* ga0 = (const float*)d_in[5];
    const float* be0 = (const float*)d_in[6];
    const float* Ws1 = (const float*)d_in[7];
    const float* Wn1 = (const float*)d_in[8];
    const float* ga1 = (const float*)d_in[9];
    const float* be1 = (const float*)d_in[10];
    const float* Ws2 = (const float*)d_in[11];
    const float* Wn2 = (const float*)d_in[12];
    const float* b2  = (const float*)d_in[13];
    float* out = (float*)d_out;

    cudaFuncSetAttribute(k_gemm01mma, cudaFuncAttributeMaxDynamicSharedMemorySize, MM_TOT);
    cudaFuncSetAttribute(k_gemm2mma,  cudaFuncAttributeMaxDynamicSharedMemorySize, M2_TOT);

    const int TB = 256;
    const int AGG_BLOCKS = (NE / EB * 32 + TB - 1) / TB;
    // slot 4 = k_gemm01mma (profiled this round)
    k_zero0<<<(NDV * H / 4 + TB - 1) / TB, TB>>>();                             // 1
    k_deg<<<(NE + TB - 1) / TB, TB>>>(dst);                                     // 2
    k_agg<<<AGG_BLOCKS, TB>>>(src, dst, feat, 0);                               // 3
    k_gemm01mma<<<148, 256, MM_TOT>>>(feat, 0, Ws0, Wn0);                       // 4 <- profiled
    k_bnfin<<<1, 128>>>(ga0, be0);
    k_apply<<<(NDV * 32 + TB - 1) / TB, TB>>>();

    // ---- layer 1 ----
    k_zero_agg<<<(NDV * H / 4 + TB - 1) / TB, TB>>>();
    k_agg<<<AGG_BLOCKS, TB>>>(src, dst, nullptr, 1);
    k_gemm01mma<<<148, 256, MM_TOT>>>(nullptr, 1, Ws1, Wn1);
    k_bnfin<<<1, 128>>>(ga1, be1);
    k_apply<<<(NDV * 32 + TB - 1) / TB, TB>>>();

    // ---- layer 2 ----
    k_gemm2mma<<<148, 256, M2_TOT>>>(Ws2, Wn2, b2, out);
    k_edge2<<<((NE / 4) * 10 + TB - 1) / TB, TB>>>(src, dst, out);

    (void)in_sizes; (void)n_in; (void)out_size;
}